// round 3
// baseline (speedup 1.0000x reference)
#include <cuda_runtime.h>

#define T_ 16
#define S_ 16
#define W_ 10
#define D_ 512
#define C_ 64
#define K_ 512
#define SW 160        // S_*W_
#define TWOD 1024
#define NP 3072       // 3 * TWOD
#define NIDX (T_ * W_ * 3 * K_)   // 245760 indices

// Scratch (device globals — no allocation allowed)
__device__ float g_W1r[D_ * NP];          // 512 x 3072  rearranged W1
__device__ float g_P[T_ * SW * NP];       // 2560 x 3072 precomputed X@W1 (per slot)
__device__ float g_r[T_ * W_ * TWOD];     // 160 x 1024  sum_k relu(z)
__device__ float g_g[T_ * W_ * D_];       // 160 x 512
__device__ float g_h3[T_ * W_ * TWOD];    // 160 x 1024
__device__ float g_o[T_ * W_ * D_];       // 160 x 512
__device__ int   g_idx[NIDX];             // normalized int32 indices
__device__ unsigned int g_oddor;          // dtype probe result

// ---------------------------------------------------------------------------
// dtype probe: OR all odd 32-bit words of the first NIDX words.
// int64 layout -> all odd words are high halves of small indices -> 0.
// int32 layout -> odd words are real indices in [0,160) -> OR != 0 (w.h.p.)
__global__ void probe_reset() { g_oddor = 0u; }

__global__ void probe_idx(const unsigned int* __restrict__ raw) {
    unsigned int v = 0;
    for (int i = blockIdx.x * 256 + threadIdx.x; i < NIDX / 2; i += gridDim.x * 256)
        v |= raw[2 * i + 1];
#pragma unroll
    for (int off = 16; off > 0; off >>= 1) v |= __shfl_xor_sync(0xffffffffu, v, off);
    if ((threadIdx.x & 31) == 0 && v) atomicOr(&g_oddor, v);
}

// normalize to int32 (+ clamp so bad data shows as rel_err, not a crash)
__global__ void norm_idx(const int* __restrict__ raw) {
    int i = blockIdx.x * 256 + threadIdx.x;
    if (i >= NIDX) return;
    int v = (g_oddor != 0u) ? raw[i] : raw[2 * i];   // int32 : int64(low word)
    v = min(max(v, 0), SW - 1);
    g_idx[i] = v;
}

// ---------------------------------------------------------------------------
// W1 (1536 x 1024) -> W1r (512 x 3072): W1r[c][s*1024+o] = W1[s*512+c][o]
__global__ void prep_w1r(const float* __restrict__ W1) {
    int idx = blockIdx.x * 256 + threadIdx.x;
    if (idx >= D_ * NP) return;
    int c = idx / NP;
    int n = idx - c * NP;
    int s = n >> 10;
    int o = n & 1023;
    g_W1r[idx] = W1[(size_t)(s * D_ + c) * TWOD + o];
}

// ---------------------------------------------------------------------------
// 128x128x8 fp32 tiled GEMM: C = A(MxK) @ B(KxN). Requires M%128==0, N%128==0, K%8==0.
__global__ __launch_bounds__(256) void gemm128(const float* __restrict__ A,
                                               const float* __restrict__ B,
                                               float* __restrict__ Cm,
                                               int M, int N, int Kd) {
    __shared__ float As[8][128];
    __shared__ float Bs[8][128];
    int col0 = blockIdx.x * 128;
    int row0 = blockIdx.y * 128;
    int tid = threadIdx.x;
    int tx = tid & 15, ty = tid >> 4;

    float acc[8][8];
#pragma unroll
    for (int i = 0; i < 8; i++)
#pragma unroll
        for (int j = 0; j < 8; j++) acc[i][j] = 0.f;

    int ar = tid >> 1, akq = (tid & 1) * 4;
    int bk = tid >> 5, bc4 = (tid & 31) * 4;

    for (int k0 = 0; k0 < Kd; k0 += 8) {
        float4 av = *(const float4*)(A + (size_t)(row0 + ar) * Kd + k0 + akq);
        As[akq + 0][ar] = av.x;
        As[akq + 1][ar] = av.y;
        As[akq + 2][ar] = av.z;
        As[akq + 3][ar] = av.w;
        *(float4*)&Bs[bk][bc4] = *(const float4*)(B + (size_t)(k0 + bk) * N + col0 + bc4);
        __syncthreads();
#pragma unroll
        for (int kk = 0; kk < 8; kk++) {
            float a[8], b[8];
            *(float4*)&a[0] = *(const float4*)&As[kk][ty * 8];
            *(float4*)&a[4] = *(const float4*)&As[kk][ty * 8 + 4];
            *(float4*)&b[0] = *(const float4*)&Bs[kk][tx * 8];
            *(float4*)&b[4] = *(const float4*)&Bs[kk][tx * 8 + 4];
#pragma unroll
            for (int i = 0; i < 8; i++)
#pragma unroll
                for (int j = 0; j < 8; j++) acc[i][j] = fmaf(a[i], b[j], acc[i][j]);
        }
        __syncthreads();
    }
#pragma unroll
    for (int i = 0; i < 8; i++) {
        int row = row0 + ty * 8 + i;
        float* cp = Cm + (size_t)row * N + col0 + tx * 8;
        float4 v0 = {acc[i][0], acc[i][1], acc[i][2], acc[i][3]};
        float4 v1 = {acc[i][4], acc[i][5], acc[i][6], acc[i][7]};
        *(float4*)cp = v0;
        *(float4*)(cp + 4) = v1;
    }
}

// ---------------------------------------------------------------------------
__global__ void zero_r() {
    int idx = blockIdx.x * 256 + threadIdx.x;
    if (idx < T_ * W_ * TWOD) g_r[idx] = 0.f;
}

// ---------------------------------------------------------------------------
// Gather + relu + k-accumulate: r[t,w,:] += sum_k relu(P1[a]+P2[b]+P3[c]+b1)
// grid: (K_/128, W_, T_), block 256 (each thread handles 4 contiguous columns)
__global__ __launch_bounds__(256) void gather_kernel(const float* __restrict__ b1) {
    int t = blockIdx.z, w = blockIdx.y, kc = blockIdx.x;
    __shared__ int sidx[3][128];
    int tid = threadIdx.x;
    for (int e = tid; e < 3 * 128; e += 256) {
        int slot = e >> 7, k = e & 127;
        sidx[slot][k] = g_idx[((t * W_ + w) * 3 + slot) * K_ + kc * 128 + k];
    }
    __syncthreads();

    int col = tid * 4;
    float4 bb = *(const float4*)(b1 + col);
    float4 acc = {0.f, 0.f, 0.f, 0.f};
    const float* Pt = g_P + (size_t)t * SW * NP;

#pragma unroll 2
    for (int k = 0; k < 128; k++) {
        const float4 pa = *(const float4*)(Pt + (size_t)sidx[0][k] * NP + col);
        const float4 pb = *(const float4*)(Pt + (size_t)sidx[1][k] * NP + 1024 + col);
        const float4 pc = *(const float4*)(Pt + (size_t)sidx[2][k] * NP + 2048 + col);
        float z;
        z = pa.x + pb.x + pc.x + bb.x; acc.x += fmaxf(z, 0.f);
        z = pa.y + pb.y + pc.y + bb.y; acc.y += fmaxf(z, 0.f);
        z = pa.z + pb.z + pc.z + bb.z; acc.z += fmaxf(z, 0.f);
        z = pa.w + pb.w + pc.w + bb.w; acc.w += fmaxf(z, 0.f);
    }
    float* rp = g_r + (size_t)(t * W_ + w) * TWOD + col;
    atomicAdd(rp + 0, acc.x);
    atomicAdd(rp + 1, acc.y);
    atomicAdd(rp + 2, acc.z);
    atomicAdd(rp + 3, acc.w);
}

// ---------------------------------------------------------------------------
// Small-M tiled GEMM with bias (scaled) and optional relu.
// BM=32, BN=64, BK=16, TM=2, TN=4, 256 threads. Requires N%64==0, K%16==0.
template <bool RELU>
__global__ __launch_bounds__(256) void gemm_small(const float* __restrict__ A,
                                                  const float* __restrict__ B,
                                                  const float* __restrict__ bias,
                                                  float bscale,
                                                  float* __restrict__ Cm,
                                                  int M, int N, int Kd) {
    __shared__ float As[16][33];
    __shared__ float Bs[16][64];
    int col0 = blockIdx.x * 64;
    int row0 = blockIdx.y * 32;
    int tid = threadIdx.x;
    int tx = tid & 15, ty = tid >> 4;
    float acc[2][4] = {};

    for (int k0 = 0; k0 < Kd; k0 += 16) {
#pragma unroll
        for (int l = 0; l < 2; l++) {
            int e = tid + l * 256;
            int m = e >> 4, kk = e & 15;
            int row = row0 + m;
            float v = 0.f;
            if (row < M) v = A[(size_t)row * Kd + k0 + kk];
            As[kk][m] = v;
        }
        {
            int kk = tid >> 4, c = (tid & 15) * 4;
            *(float4*)&Bs[kk][c] = *(const float4*)(B + (size_t)(k0 + kk) * N + col0 + c);
        }
        __syncthreads();
#pragma unroll
        for (int kk = 0; kk < 16; kk++) {
            float a0 = As[kk][ty * 2], a1 = As[kk][ty * 2 + 1];
            float4 b = *(const float4*)&Bs[kk][tx * 4];
            acc[0][0] = fmaf(a0, b.x, acc[0][0]);
            acc[0][1] = fmaf(a0, b.y, acc[0][1]);
            acc[0][2] = fmaf(a0, b.z, acc[0][2]);
            acc[0][3] = fmaf(a0, b.w, acc[0][3]);
            acc[1][0] = fmaf(a1, b.x, acc[1][0]);
            acc[1][1] = fmaf(a1, b.y, acc[1][1]);
            acc[1][2] = fmaf(a1, b.z, acc[1][2]);
            acc[1][3] = fmaf(a1, b.w, acc[1][3]);
        }
        __syncthreads();
    }
#pragma unroll
    for (int i = 0; i < 2; i++) {
        int row = row0 + ty * 2 + i;
        if (row >= M) continue;
#pragma unroll
        for (int j = 0; j < 4; j++) {
            int col = col0 + tx * 4 + j;
            float v = acc[i][j] + bias[col] * bscale;
            if (RELU) v = fmaxf(v, 0.f);
            Cm[(size_t)row * N + col] = v;
        }
    }
}

// ---------------------------------------------------------------------------
// score = o @ Wc + bc, then softmax over C_=64. One block (64 threads) per row.
__global__ __launch_bounds__(64) void score_softmax(const float* __restrict__ Wc,
                                                    const float* __restrict__ bc,
                                                    float* __restrict__ out) {
    int row = blockIdx.x;
    int tid = threadIdx.x;
    __shared__ float so[D_];
    for (int e = tid; e < D_; e += 64) so[e] = g_o[(size_t)row * D_ + e];
    __syncthreads();

    float acc = bc[tid];
#pragma unroll 4
    for (int k = 0; k < D_; k++) acc = fmaf(so[k], Wc[(size_t)k * C_ + tid], acc);

    __shared__ float red[2], red2[2];
    float m = acc;
#pragma unroll
    for (int off = 16; off > 0; off >>= 1) m = fmaxf(m, __shfl_xor_sync(0xffffffffu, m, off));
    if ((tid & 31) == 0) red[tid >> 5] = m;
    __syncthreads();
    m = fmaxf(red[0], red[1]);

    float e = expf(acc - m);
    float s = e;
#pragma unroll
    for (int off = 16; off > 0; off >>= 1) s += __shfl_xor_sync(0xffffffffu, s, off);
    if ((tid & 31) == 0) red2[tid >> 5] = s;
    __syncthreads();
    s = red2[0] + red2[1];

    out[(size_t)row * C_ + tid] = e / s;
}

// ---------------------------------------------------------------------------
extern "C" void kernel_launch(void* const* d_in, const int* in_sizes, int n_in,
                              void* d_out, int out_size) {
    const float* x    = (const float*)d_in[0];
    const void*  tidx = d_in[1];                 // int32 or int64 — probed on device
    const float* W1   = (const float*)d_in[2];
    const float* b1   = (const float*)d_in[3];
    const float* W2   = (const float*)d_in[4];
    const float* b2   = (const float*)d_in[5];
    const float* W3   = (const float*)d_in[6];
    const float* b3   = (const float*)d_in[7];
    const float* W4   = (const float*)d_in[8];
    const float* bc   = (const float*)d_in[11];
    const float* Wc   = (const float*)d_in[10];
    const float* b4   = (const float*)d_in[9];
    float* out = (float*)d_out;

    void *pW1r, *pP, *pr, *pg, *ph3, *po;
    cudaGetSymbolAddress(&pW1r, g_W1r);
    cudaGetSymbolAddress(&pP, g_P);
    cudaGetSymbolAddress(&pr, g_r);
    cudaGetSymbolAddress(&pg, g_g);
    cudaGetSymbolAddress(&ph3, g_h3);
    cudaGetSymbolAddress(&po, g_o);

    // 0) probe index dtype + normalize to int32
    probe_reset<<<1, 1>>>();
    probe_idx<<<120, 256>>>((const unsigned int*)tidx);
    norm_idx<<<(NIDX + 255) / 256, 256>>>((const int*)tidx);

    // 1) rearrange W1
    prep_w1r<<<(D_ * NP + 255) / 256, 256>>>(W1);

    // 2) P = X @ W1r   (2560 x 3072, K=512)
    gemm128<<<dim3(NP / 128, (T_ * SW) / 128), 256>>>(
        x, (const float*)pW1r, (float*)pP, T_ * SW, NP, D_);

    // 3) zero r, then gather+relu+sum over k (atomic accumulate across k-chunks)
    zero_r<<<(T_ * W_ * TWOD + 255) / 256, 256>>>();
    gather_kernel<<<dim3(K_ / 128, W_, T_), 256>>>(b1);

    // 4) g = r @ W2 + K_*b2        (160 x 512, K=1024)
    gemm_small<false><<<dim3(D_ / 64, (T_ * W_ + 31) / 32), 256>>>(
        (const float*)pr, W2, b2, (float)K_, (float*)pg, T_ * W_, D_, TWOD);

    // 5) h3 = relu(g @ W3 + b3)    (160 x 1024, K=512)
    gemm_small<true><<<dim3(TWOD / 64, (T_ * W_ + 31) / 32), 256>>>(
        (const float*)pg, W3, b3, 1.f, (float*)ph3, T_ * W_, TWOD, D_);

    // 6) o = h3 @ W4 + b4          (160 x 512, K=1024)
    gemm_small<false><<<dim3(D_ / 64, (T_ * W_ + 31) / 32), 256>>>(
        (const float*)ph3, W4, b4, 1.f, (float*)po, T_ * W_, D_, TWOD);

    // 7) score + softmax -> out    (160 x 64)
    score_softmax<<<T_ * W_, 64>>>(Wc, bc, out);
}

// round 5
// speedup vs baseline: 1.3710x; 1.3710x over previous
#include <cuda_runtime.h>
#include <cuda_fp16.h>
#include <mma.h>
#include <cstdint>

using namespace nvcuda;

#define T_ 16
#define S_ 16
#define W_ 10
#define D_ 512
#define C_ 64
#define K_ 512
#define SW 160        // S_*W_
#define TWOD 1024
#define NP 3072       // 3 * TWOD
#define NIDX (T_ * W_ * 3 * K_)   // 245760 indices
#define M_ (T_ * SW)              // 2560 rows of P

// ---------------------------------------------------------------------------
// Device globals (no allocation allowed)
__device__ __half g_Bh[NP * D_];          // B^T hi  [3072][512] (fp16)
__device__ __half g_Bl[NP * D_];          // B^T lo  [3072][512] (fp16)
__device__ __half g_Ph[(size_t)M_ * NP];  // P in fp16  [2560][3072]
__device__ float g_r[T_ * W_ * TWOD];     // 160 x 1024  sum_k relu(z)
__device__ float g_g[T_ * W_ * D_];       // 160 x 512
__device__ float g_h3[T_ * W_ * TWOD];    // 160 x 1024
__device__ float g_o[T_ * W_ * D_];       // 160 x 512
__device__ int   g_idx[NIDX];             // normalized int32 indices
__device__ unsigned int g_oddor;          // dtype probe result

// ---------------------------------------------------------------------------
// dtype probe + index normalization (int64 vs int32 robustness)
__global__ void probe_reset() { g_oddor = 0u; }

__global__ void probe_idx(const unsigned int* __restrict__ raw) {
    unsigned int v = 0;
    for (int i = blockIdx.x * 256 + threadIdx.x; i < NIDX / 2; i += gridDim.x * 256)
        v |= raw[2 * i + 1];
#pragma unroll
    for (int off = 16; off > 0; off >>= 1) v |= __shfl_xor_sync(0xffffffffu, v, off);
    if ((threadIdx.x & 31) == 0 && v) atomicOr(&g_oddor, v);
}

__global__ void norm_idx(const int* __restrict__ raw) {
    int i = blockIdx.x * 256 + threadIdx.x;
    if (i >= NIDX) return;
    int v = (g_oddor != 0u) ? raw[i] : raw[2 * i];
    v = min(max(v, 0), SW - 1);
    g_idx[i] = v;
}

// ---------------------------------------------------------------------------
// W1 (1536 x 1024) -> B^T hi/lo fp16 [3072][512]: Bt[n][k] = W1[s*512+k][o], n=s*1024+o
__global__ void prep_b(const float* __restrict__ W1) {
    int i = blockIdx.x * 256 + threadIdx.x;
    if (i >= NP * D_) return;
    int n = i >> 9;
    int k = i & 511;
    int s = n >> 10, o = n & 1023;
    float v = W1[(size_t)(s * D_ + k) * TWOD + o];
    __half h = __float2half_rn(v);
    g_Bh[i] = h;
    g_Bl[i] = __float2half_rn(v - __half2float(h));
}

// ---------------------------------------------------------------------------
// Split-fp16 WMMA GEMM: P(fp16) = A(fp32 2560x512) @ Bt^T (3072 x 512)
// CTA tile 128x128, 8 warps (warp tile 32x64), K-chunks of 32.
// P = Ah*Bh + Ah*Bl + Al*Bh (fp32 accum); Al*Bl (~2^-22) dropped.
#define KPAD 40

__global__ __launch_bounds__(256, 1) void gemm_wmma(const float* __restrict__ A) {
    __shared__ __align__(32) __half Ah[128][KPAD];
    __shared__ __align__(32) __half Al[128][KPAD];
    __shared__ __align__(32) __half Bh[128][KPAD];
    __shared__ __align__(32) __half Bl[128][KPAD];

    int tid = threadIdx.x;
    int wid = tid >> 5, lane = tid & 31;
    int warp_m = wid & 3;    // 4 warps along M -> 32 rows each
    int warp_n = wid >> 2;   // 2 warps along N -> 64 cols each
    int row0 = blockIdx.y * 128;
    int col0 = blockIdx.x * 128;

    wmma::fragment<wmma::accumulator, 16, 16, 16, float> acc[2][4];
#pragma unroll
    for (int i = 0; i < 2; i++)
#pragma unroll
        for (int j = 0; j < 4; j++) wmma::fill_fragment(acc[i][j], 0.f);

    for (int c = 0; c < D_ / 32; c++) {
        int k0 = c * 32;
        // A chunk: 128 rows x 32 fp32 -> fp16 hi/lo. 1024 float4, 4 per thread.
#pragma unroll
        for (int j = 0; j < 4; j++) {
            int idx = tid + j * 256;
            int r = idx >> 3;
            int cq = (idx & 7) * 4;
            float4 v = *(const float4*)(A + (size_t)(row0 + r) * D_ + k0 + cq);
            __half h0 = __float2half_rn(v.x), h1 = __float2half_rn(v.y);
            __half h2 = __float2half_rn(v.z), h3 = __float2half_rn(v.w);
            __half l0 = __float2half_rn(v.x - __half2float(h0));
            __half l1 = __float2half_rn(v.y - __half2float(h1));
            __half l2 = __float2half_rn(v.z - __half2float(h2));
            __half l3 = __float2half_rn(v.w - __half2float(h3));
            __half2 hh0; hh0.x = h0; hh0.y = h1;
            __half2 hh1; hh1.x = h2; hh1.y = h3;
            __half2 ll0; ll0.x = l0; ll0.y = l1;
            __half2 ll1; ll1.x = l2; ll1.y = l3;
            *(__half2*)&Ah[r][cq] = hh0;
            *(__half2*)&Ah[r][cq + 2] = hh1;
            *(__half2*)&Al[r][cq] = ll0;
            *(__half2*)&Al[r][cq + 2] = ll1;
        }
        // B chunks: 128 rows x 32 fp16 each (hi, lo). 512 uint4 per matrix, 2/thread.
#pragma unroll
        for (int j = 0; j < 2; j++) {
            int idx = tid + j * 256;
            int r = idx >> 2;
            int q = (idx & 3) * 8;
            *(uint4*)&Bh[r][q] = *(const uint4*)(g_Bh + (size_t)(col0 + r) * D_ + k0 + q);
            *(uint4*)&Bl[r][q] = *(const uint4*)(g_Bl + (size_t)(col0 + r) * D_ + k0 + q);
        }
        __syncthreads();

#pragma unroll
        for (int kk = 0; kk < 32; kk += 16) {
            wmma::fragment<wmma::matrix_a, 16, 16, 16, __half, wmma::row_major> fah[2], fal[2];
            wmma::fragment<wmma::matrix_b, 16, 16, 16, __half, wmma::col_major> fbh[4], fbl[4];
#pragma unroll
            for (int i = 0; i < 2; i++) {
                wmma::load_matrix_sync(fah[i], &Ah[warp_m * 32 + i * 16][kk], KPAD);
                wmma::load_matrix_sync(fal[i], &Al[warp_m * 32 + i * 16][kk], KPAD);
            }
#pragma unroll
            for (int j = 0; j < 4; j++) {
                wmma::load_matrix_sync(fbh[j], &Bh[warp_n * 64 + j * 16][kk], KPAD);
                wmma::load_matrix_sync(fbl[j], &Bl[warp_n * 64 + j * 16][kk], KPAD);
            }
#pragma unroll
            for (int i = 0; i < 2; i++)
#pragma unroll
                for (int j = 0; j < 4; j++) {
                    wmma::mma_sync(acc[i][j], fah[i], fbh[j], acc[i][j]);
                    wmma::mma_sync(acc[i][j], fah[i], fbl[j], acc[i][j]);
                    wmma::mma_sync(acc[i][j], fal[i], fbh[j], acc[i][j]);
                }
        }
        __syncthreads();
    }

    // Epilogue: per-warp 16x16 float patch in (now free) Ah smem, convert to fp16.
    __syncthreads();
    float* patch = (float*)&Ah[0][0] + wid * 256;   // 8 warps x 1KB inside 10KB Ah
#pragma unroll
    for (int i = 0; i < 2; i++)
#pragma unroll
        for (int j = 0; j < 4; j++) {
            wmma::store_matrix_sync(patch, acc[i][j], 16, wmma::mem_row_major);
            __syncwarp();
            int m = row0 + warp_m * 32 + i * 16;
            int n = col0 + warp_n * 64 + j * 16;
            int pr = lane >> 1, pc = (lane & 1) * 8;
            __half2 o[4];
#pragma unroll
            for (int e = 0; e < 4; e++)
                o[e] = __floats2half2_rn(patch[pr * 16 + pc + 2 * e],
                                         patch[pr * 16 + pc + 2 * e + 1]);
            *(uint4*)(g_Ph + (size_t)(m + pr) * NP + n + pc) = *(uint4*)o;
            __syncwarp();
        }
}

// ---------------------------------------------------------------------------
__global__ void zero_r() {
    int idx = blockIdx.x * 256 + threadIdx.x;
    if (idx < T_ * W_ * TWOD) g_r[idx] = 0.f;
}

// ---------------------------------------------------------------------------
// Gather + relu + k-accumulate on fp16 P. grid (K_/128, W_, T_), 128 threads x 8 cols.
__global__ __launch_bounds__(128) void gather_h(const float* __restrict__ b1) {
    int t = blockIdx.z, w = blockIdx.y, kc = blockIdx.x;
    __shared__ int sidx[3][128];
    int tid = threadIdx.x;
    for (int e = tid; e < 3 * 128; e += 128) {
        int slot = e >> 7, k = e & 127;
        sidx[slot][k] = g_idx[((t * W_ + w) * 3 + slot) * K_ + kc * 128 + k];
    }
    __syncthreads();

    int col = tid * 8;
    float bb[8];
#pragma unroll
    for (int j = 0; j < 8; j++) bb[j] = b1[col + j];
    float acc[8] = {0.f, 0.f, 0.f, 0.f, 0.f, 0.f, 0.f, 0.f};
    const __half* Pt = g_Ph + (size_t)t * SW * NP;

#pragma unroll 2
    for (int k = 0; k < 128; k++) {
        uint4 va = *(const uint4*)(Pt + (size_t)sidx[0][k] * NP + col);
        uint4 vb = *(const uint4*)(Pt + (size_t)sidx[1][k] * NP + 1024 + col);
        uint4 vc = *(const uint4*)(Pt + (size_t)sidx[2][k] * NP + 2048 + col);
        const __half2* ha = (const __half2*)&va;
        const __half2* hb = (const __half2*)&vb;
        const __half2* hc = (const __half2*)&vc;
#pragma unroll
        for (int j = 0; j < 4; j++) {
            float2 fa = __half22float2(ha[j]);
            float2 fb = __half22float2(hb[j]);
            float2 fc = __half22float2(hc[j]);
            float z0 = fa.x + fb.x + fc.x + bb[2 * j];
            float z1 = fa.y + fb.y + fc.y + bb[2 * j + 1];
            acc[2 * j]     += fmaxf(z0, 0.f);
            acc[2 * j + 1] += fmaxf(z1, 0.f);
        }
    }
    float* rp = g_r + (size_t)(t * W_ + w) * TWOD + col;
#pragma unroll
    for (int j = 0; j < 8; j++) atomicAdd(rp + j, acc[j]);
}

// ---------------------------------------------------------------------------
// Small-M tiled GEMM with bias (scaled) and optional relu.
template <bool RELU>
__global__ __launch_bounds__(256) void gemm_small(const float* __restrict__ A,
                                                  const float* __restrict__ B,
                                                  const float* __restrict__ bias,
                                                  float bscale,
                                                  float* __restrict__ Cm,
                                                  int M, int N, int Kd) {
    __shared__ float As[16][33];
    __shared__ float Bs[16][64];
    int col0 = blockIdx.x * 64;
    int row0 = blockIdx.y * 32;
    int tid = threadIdx.x;
    int tx = tid & 15, ty = tid >> 4;
    float acc[2][4] = {};

    for (int k0 = 0; k0 < Kd; k0 += 16) {
#pragma unroll
        for (int l = 0; l < 2; l++) {
            int e = tid + l * 256;
            int m = e >> 4, kk = e & 15;
            int row = row0 + m;
            float v = 0.f;
            if (row < M) v = A[(size_t)row * Kd + k0 + kk];
            As[kk][m] = v;
        }
        {
            int kk = tid >> 4, c = (tid & 15) * 4;
            *(float4*)&Bs[kk][c] = *(const float4*)(B + (size_t)(k0 + kk) * N + col0 + c);
        }
        __syncthreads();
#pragma unroll
        for (int kk = 0; kk < 16; kk++) {
            float a0 = As[kk][ty * 2], a1 = As[kk][ty * 2 + 1];
            float4 b = *(const float4*)&Bs[kk][tx * 4];
            acc[0][0] = fmaf(a0, b.x, acc[0][0]);
            acc[0][1] = fmaf(a0, b.y, acc[0][1]);
            acc[0][2] = fmaf(a0, b.z, acc[0][2]);
            acc[0][3] = fmaf(a0, b.w, acc[0][3]);
            acc[1][0] = fmaf(a1, b.x, acc[1][0]);
            acc[1][1] = fmaf(a1, b.y, acc[1][1]);
            acc[1][2] = fmaf(a1, b.z, acc[1][2]);
            acc[1][3] = fmaf(a1, b.w, acc[1][3]);
        }
        __syncthreads();
    }
#pragma unroll
    for (int i = 0; i < 2; i++) {
        int row = row0 + ty * 2 + i;
        if (row >= M) continue;
#pragma unroll
        for (int j = 0; j < 4; j++) {
            int colx = col0 + tx * 4 + j;
            float v = acc[i][j] + bias[colx] * bscale;
            if (RELU) v = fmaxf(v, 0.f);
            Cm[(size_t)row * N + colx] = v;
        }
    }
}

// ---------------------------------------------------------------------------
// score = o @ Wc + bc, softmax over C_=64. One block (64 threads) per row.
__global__ __launch_bounds__(64) void score_softmax(const float* __restrict__ Wc,
                                                    const float* __restrict__ bc,
                                                    float* __restrict__ out) {
    int row = blockIdx.x;
    int tid = threadIdx.x;
    __shared__ float so[D_];
    for (int e = tid; e < D_; e += 64) so[e] = g_o[(size_t)row * D_ + e];
    __syncthreads();

    float acc = bc[tid];
#pragma unroll 4
    for (int k = 0; k < D_; k++) acc = fmaf(so[k], Wc[(size_t)k * C_ + tid], acc);

    __shared__ float red[2], red2[2];
    float m = acc;
#pragma unroll
    for (int off = 16; off > 0; off >>= 1) m = fmaxf(m, __shfl_xor_sync(0xffffffffu, m, off));
    if ((tid & 31) == 0) red[tid >> 5] = m;
    __syncthreads();
    m = fmaxf(red[0], red[1]);

    float e = expf(acc - m);
    float s = e;
#pragma unroll
    for (int off = 16; off > 0; off >>= 1) s += __shfl_xor_sync(0xffffffffu, s, off);
    if ((tid & 31) == 0) red2[tid >> 5] = s;
    __syncthreads();
    s = red2[0] + red2[1];

    out[(size_t)row * C_ + tid] = e / s;
}

// ---------------------------------------------------------------------------
extern "C" void kernel_launch(void* const* d_in, const int* in_sizes, int n_in,
                              void* d_out, int out_size) {
    const float* x    = (const float*)d_in[0];
    const void*  tidx = d_in[1];                 // int32 or int64 — probed on device
    const float* W1   = (const float*)d_in[2];
    const float* b1   = (const float*)d_in[3];
    const float* W2   = (const float*)d_in[4];
    const float* b2   = (const float*)d_in[5];
    const float* W3   = (const float*)d_in[6];
    const float* b3   = (const float*)d_in[7];
    const float* W4   = (const float*)d_in[8];
    const float* b4   = (const float*)d_in[9];
    const float* Wc   = (const float*)d_in[10];
    const float* bc   = (const float*)d_in[11];
    float* out = (float*)d_out;

    void *pr, *pg, *ph3, *po;
    cudaGetSymbolAddress(&pr, g_r);
    cudaGetSymbolAddress(&pg, g_g);
    cudaGetSymbolAddress(&ph3, g_h3);
    cudaGetSymbolAddress(&po, g_o);

    // 0) probe index dtype + normalize to int32
    probe_reset<<<1, 1>>>();
    probe_idx<<<120, 256>>>((const unsigned int*)tidx);
    norm_idx<<<(NIDX + 255) / 256, 256>>>((const int*)tidx);

    // 1) W1 -> fp16 hi/lo transposed B
    prep_b<<<(NP * D_ + 255) / 256, 256>>>(W1);

    // 2) P(fp16) = X @ W1r via split-fp16 WMMA (3 mma terms, fp32 accum)
    gemm_wmma<<<dim3(NP / 128, M_ / 128), 256>>>(x);

    // 3) zero r, then gather+relu+sum over k
    zero_r<<<(T_ * W_ * TWOD + 255) / 256, 256>>>();
    gather_h<<<dim3(K_ / 128, W_, T_), 128>>>(b1);

    // 4) g = r @ W2 + K_*b2        (160 x 512, K=1024)
    gemm_small<false><<<dim3(D_ / 64, (T_ * W_ + 31) / 32), 256>>>(
        (const float*)pr, W2, b2, (float)K_, (float*)pg, T_ * W_, D_, TWOD);

    // 5) h3 = relu(g @ W3 + b3)    (160 x 1024, K=512)
    gemm_small<true><<<dim3(TWOD / 64, (T_ * W_ + 31) / 32), 256>>>(
        (const float*)pg, W3, b3, 1.f, (float*)ph3, T_ * W_, TWOD, D_);

    // 6) o = h3 @ W4 + b4          (160 x 512, K=1024)
    gemm_small<false><<<dim3(D_ / 64, (T_ * W_ + 31) / 32), 256>>>(
        (const float*)ph3, W4, b4, 1.f, (float*)po, T_ * W_, D_, TWOD);

    // 7) score + softmax -> out    (160 x 64)
    score_softmax<<<T_ * W_, 64>>>(Wc, bc, out);
}

// round 8
// speedup vs baseline: 1.6612x; 1.2117x over previous
#include <cuda_runtime.h>
#include <cuda_fp16.h>
#include <mma.h>
#include <cstdint>

using namespace nvcuda;

#define T_ 16
#define S_ 16
#define W_ 10
#define D_ 512
#define C_ 64
#define K_ 512
#define SW 160        // S_*W_
#define TWOD 1024
#define NP 3072       // 3 * TWOD
#define NIDX (T_ * W_ * 3 * K_)   // 245760 indices
#define M_ (T_ * SW)              // 2560 rows of P
#define KK 1536                   // concat K: [Ah|Ah|Al] . [Bh|Bl|Bh]

// ---------------------------------------------------------------------------
// Device globals (no allocation allowed)
__device__ __half g_A3[(size_t)M_ * KK];  // [2560][1536] fp16 concat A
__device__ __half g_B3[(size_t)NP * KK];  // [3072][1536] fp16 concat B^T
__device__ __half g_Ph[(size_t)M_ * NP];  // P in fp16  [2560][3072]
__device__ float g_r[T_ * W_ * TWOD];     // 160 x 1024  sum_k relu(z)
__device__ float g_g[T_ * W_ * D_];       // 160 x 512
__device__ float g_h3[T_ * W_ * TWOD];    // 160 x 1024 (pre-relu)
__device__ float g_o[T_ * W_ * D_];       // 160 x 512
__device__ int   g_idx[NIDX];             // normalized int32 indices
__device__ unsigned int g_oddor;          // dtype probe result

// ---------------------------------------------------------------------------
__device__ __forceinline__ void cp_async16(void* dst, const void* src) {
    uint32_t d;
    asm("{ .reg .u64 t; cvta.to.shared.u64 t, %1; cvt.u32.u64 %0, t; }" : "=r"(d) : "l"(dst));
    asm volatile("cp.async.cg.shared.global [%0], [%1], 16;" :: "r"(d), "l"(src));
}

// ---------------------------------------------------------------------------
// dtype probe + index normalization (int64 vs int32 robustness)
__global__ void probe_reset() { g_oddor = 0u; }

__global__ void probe_idx(const unsigned int* __restrict__ raw) {
    unsigned int v = 0;
    for (int i = blockIdx.x * 256 + threadIdx.x; i < NIDX / 2; i += gridDim.x * 256)
        v |= raw[2 * i + 1];
#pragma unroll
    for (int off = 16; off > 0; off >>= 1) v |= __shfl_xor_sync(0xffffffffu, v, off);
    if ((threadIdx.x & 31) == 0 && v) atomicOr(&g_oddor, v);
}

__global__ void norm_idx(const int* __restrict__ raw) {
    int i = blockIdx.x * 256 + threadIdx.x;
    if (i >= NIDX) return;
    int v = (g_oddor != 0u) ? raw[i] : raw[2 * i];
    v = min(max(v, 0), SW - 1);
    g_idx[i] = v;
}

// ---------------------------------------------------------------------------
// X (2560x512 fp32) -> A3 = [Ah | Ah | Al] fp16 [2560][1536]
__global__ void prep_a(const float* __restrict__ x) {
    int i = blockIdx.x * 256 + threadIdx.x;
    if (i >= M_ * D_) return;
    int m = i >> 9, k = i & 511;
    float v = x[i];
    __half h = __float2half_rn(v);
    __half l = __float2half_rn(v - __half2float(h));
    size_t base = (size_t)m * KK + k;
    g_A3[base] = h;
    g_A3[base + 512] = h;
    g_A3[base + 1024] = l;
}

// W1 (1536 x 1024) -> B3 = [Bh | Bl | Bh] fp16 [3072][1536]
// B^T[n][k] = W1[s*512+k][o], n = s*1024+o
__global__ void prep_b3(const float* __restrict__ W1) {
    int i = blockIdx.x * 256 + threadIdx.x;
    if (i >= NP * D_) return;
    int n = i >> 9, k = i & 511;
    int s = n >> 10, o = n & 1023;
    float v = W1[(size_t)(s * D_ + k) * TWOD + o];
    __half h = __float2half_rn(v);
    __half l = __float2half_rn(v - __half2float(h));
    size_t base = (size_t)n * KK + k;
    g_B3[base] = h;
    g_B3[base + 512] = l;
    g_B3[base + 1024] = h;
}

// ---------------------------------------------------------------------------
// fp16 GEMM, fp32 accum: P(fp16 2560x3072) = A3 (2560x1536) @ B3^T (3072x1536)
// CTA 128x128, 8 warps (warp tile 32x64), BK=64, 2-stage cp.async pipeline.
#define BK 64
#define KPAD 72
#define STAGE_H (128 * KPAD)         // halves per matrix per stage (9216)
#define NCH (KK / BK)                // 24 chunks

__global__ __launch_bounds__(256, 1) void gemm_fp16() {
    extern __shared__ __half sh[];   // [2 stages][A 128x72 | B 128x72]

    int tid = threadIdx.x;
    int wid = tid >> 5, lane = tid & 31;
    int warp_m = wid & 3;    // 4 warps along M -> 32 rows each
    int warp_n = wid >> 2;   // 2 warps along N -> 64 cols each
    int row0 = blockIdx.y * 128;
    int col0 = blockIdx.x * 128;

    wmma::fragment<wmma::accumulator, 16, 16, 16, float> acc[2][4];
#pragma unroll
    for (int i = 0; i < 2; i++)
#pragma unroll
        for (int j = 0; j < 4; j++) wmma::fill_fragment(acc[i][j], 0.f);

    const __half* Ag = g_A3;
    const __half* Bg = g_B3;

    auto prefetch = [&](int c) {
        __half* As = sh + (c & 1) * (2 * STAGE_H);
        __half* Bs = As + STAGE_H;
        int k0 = c * BK;
#pragma unroll
        for (int j = 0; j < 4; j++) {
            int idx = tid + j * 256;
            int r = idx >> 3, q = (idx & 7) * 8;
            cp_async16(&As[r * KPAD + q], Ag + (size_t)(row0 + r) * KK + k0 + q);
            cp_async16(&Bs[r * KPAD + q], Bg + (size_t)(col0 + r) * KK + k0 + q);
        }
        asm volatile("cp.async.commit_group;" ::: "memory");
    };

    prefetch(0);
    for (int c = 0; c < NCH; c++) {
        if (c + 1 < NCH) {
            prefetch(c + 1);
            asm volatile("cp.async.wait_group 1;" ::: "memory");
        } else {
            asm volatile("cp.async.wait_group 0;" ::: "memory");
        }
        __syncthreads();

        const __half* As = sh + (c & 1) * (2 * STAGE_H);
        const __half* Bs = As + STAGE_H;
#pragma unroll
        for (int kk = 0; kk < BK; kk += 16) {
            wmma::fragment<wmma::matrix_a, 16, 16, 16, __half, wmma::row_major> fa[2];
            wmma::fragment<wmma::matrix_b, 16, 16, 16, __half, wmma::col_major> fb[4];
#pragma unroll
            for (int i = 0; i < 2; i++)
                wmma::load_matrix_sync(fa[i], As + (warp_m * 32 + i * 16) * KPAD + kk, KPAD);
#pragma unroll
            for (int j = 0; j < 4; j++)
                wmma::load_matrix_sync(fb[j], Bs + (warp_n * 64 + j * 16) * KPAD + kk, KPAD);
#pragma unroll
            for (int i = 0; i < 2; i++)
#pragma unroll
                for (int j = 0; j < 4; j++)
                    wmma::mma_sync(acc[i][j], fa[i], fb[j], acc[i][j]);
        }
        __syncthreads();
    }

    // Epilogue: per-warp 16x16 float patch in smem, convert to fp16, store P.
    float* patch = (float*)sh + wid * 256;
#pragma unroll
    for (int i = 0; i < 2; i++)
#pragma unroll
        for (int j = 0; j < 4; j++) {
            wmma::store_matrix_sync(patch, acc[i][j], 16, wmma::mem_row_major);
            __syncwarp();
            int m = row0 + warp_m * 32 + i * 16;
            int n = col0 + warp_n * 64 + j * 16;
            int pr = lane >> 1, pc = (lane & 1) * 8;
            __half2 o[4];
#pragma unroll
            for (int e = 0; e < 4; e++)
                o[e] = __floats2half2_rn(patch[pr * 16 + pc + 2 * e],
                                         patch[pr * 16 + pc + 2 * e + 1]);
            *(uint4*)(g_Ph + (size_t)(m + pr) * NP + n + pc) = *(uint4*)o;
            __syncwarp();
        }
}

// ---------------------------------------------------------------------------
// Zero all accumulator buffers (r, g, h3, o) in one pass.
__global__ void zero_all() {
    int idx = blockIdx.x * 256 + threadIdx.x;
    if (idx < T_ * W_ * TWOD) g_r[idx] = 0.f;
    if (idx < T_ * W_ * TWOD) g_h3[idx] = 0.f;
    if (idx < T_ * W_ * D_) { g_g[idx] = 0.f; g_o[idx] = 0.f; }
}

// ---------------------------------------------------------------------------
// Gather + relu + k-accumulate on fp16 P. grid (K_/128, W_, T_), 128 threads x 8 cols.
__global__ __launch_bounds__(128) void gather_h(const float* __restrict__ b1) {
    int t = blockIdx.z, w = blockIdx.y, kc = blockIdx.x;
    __shared__ int sidx[3][128];
    int tid = threadIdx.x;
    for (int e = tid; e < 3 * 128; e += 128) {
        int slot = e >> 7, k = e & 127;
        sidx[slot][k] = g_idx[((t * W_ + w) * 3 + slot) * K_ + kc * 128 + k];
    }
    __syncthreads();

    int col = tid * 8;
    float bb[8];
#pragma unroll
    for (int j = 0; j < 8; j++) bb[j] = b1[col + j];
    float acc[8] = {0.f, 0.f, 0.f, 0.f, 0.f, 0.f, 0.f, 0.f};
    const __half* Pt = g_Ph + (size_t)t * SW * NP;

#pragma unroll 2
    for (int k = 0; k < 128; k++) {
        uint4 va = *(const uint4*)(Pt + (size_t)sidx[0][k] * NP + col);
        uint4 vb = *(const uint4*)(Pt + (size_t)sidx[1][k] * NP + 1024 + col);
        uint4 vc = *(const uint4*)(Pt + (size_t)sidx[2][k] * NP + 2048 + col);
        const __half2* ha = (const __half2*)&va;
        const __half2* hb = (const __half2*)&vb;
        const __half2* hc = (const __half2*)&vc;
#pragma unroll
        for (int j = 0; j < 4; j++) {
            float2 fa = __half22float2(ha[j]);
            float2 fb = __half22float2(hb[j]);
            float2 fc = __half22float2(hc[j]);
            float z0 = fa.x + fb.x + fc.x + bb[2 * j];
            float z1 = fa.y + fb.y + fc.y + bb[2 * j + 1];
            acc[2 * j]     += fmaxf(z0, 0.f);
            acc[2 * j + 1] += fmaxf(z1, 0.f);
        }
    }
    float* rp = g_r + (size_t)(t * W_ + w) * TWOD + col;
#pragma unroll
    for (int j = 0; j < 8; j++) atomicAdd(rp + j, acc[j]);
}

// ---------------------------------------------------------------------------
// Small-M k-split GEMM: Cm += A[k-slice] @ B[k-slice] (atomicAdd), bias from z==0.
// RELUA applies relu to A elements on load. BM=32, BN=64, BK=16, 256 threads.
// Requires M%32==0, N%64==0, Kd % (16*gridDim.z) == 0.
template <bool RELUA>
__global__ __launch_bounds__(256) void gemm_ks(const float* __restrict__ A,
                                               const float* __restrict__ B,
                                               const float* __restrict__ bias,
                                               float bscale,
                                               float* __restrict__ Cm,
                                               int M, int N, int Kd) {
    __shared__ float As[16][33];
    __shared__ float Bs[16][64];
    int col0 = blockIdx.x * 64;
    int row0 = blockIdx.y * 32;
    int tid = threadIdx.x;
    int tx = tid & 15, ty = tid >> 4;
    int klen = Kd / gridDim.z;
    int kbeg = blockIdx.z * klen, kend = kbeg + klen;
    float acc[2][4] = {};

    for (int k0 = kbeg; k0 < kend; k0 += 16) {
#pragma unroll
        for (int l = 0; l < 2; l++) {
            int e = tid + l * 256;
            int m = e >> 4, kk = e & 15;
            float v = A[(size_t)(row0 + m) * Kd + k0 + kk];
            if (RELUA) v = fmaxf(v, 0.f);
            As[kk][m] = v;
        }
        {
            int kk = tid >> 4, c = (tid & 15) * 4;
            *(float4*)&Bs[kk][c] = *(const float4*)(B + (size_t)(k0 + kk) * N + col0 + c);
        }
        __syncthreads();
#pragma unroll
        for (int kk = 0; kk < 16; kk++) {
            float a0 = As[kk][ty * 2], a1 = As[kk][ty * 2 + 1];
            float4 b = *(const float4*)&Bs[kk][tx * 4];
            acc[0][0] = fmaf(a0, b.x, acc[0][0]);
            acc[0][1] = fmaf(a0, b.y, acc[0][1]);
            acc[0][2] = fmaf(a0, b.z, acc[0][2]);
            acc[0][3] = fmaf(a0, b.w, acc[0][3]);
            acc[1][0] = fmaf(a1, b.x, acc[1][0]);
            acc[1][1] = fmaf(a1, b.y, acc[1][1]);
            acc[1][2] = fmaf(a1, b.z, acc[1][2]);
            acc[1][3] = fmaf(a1, b.w, acc[1][3]);
        }
        __syncthreads();
    }
#pragma unroll
    for (int i = 0; i < 2; i++) {
        int row = row0 + ty * 2 + i;
#pragma unroll
        for (int j = 0; j < 4; j++) {
            int colx = col0 + tx * 4 + j;
            float v = acc[i][j];
            if (blockIdx.z == 0) v += bias[colx] * bscale;
            atomicAdd(&Cm[(size_t)row * N + colx], v);
        }
    }
}

// ---------------------------------------------------------------------------
// score = o @ Wc + bc, softmax over C_=64. One block (64 threads) per row.
__global__ __launch_bounds__(64) void score_softmax(const float* __restrict__ Wc,
                                                    const float* __restrict__ bc,
                                                    float* __restrict__ out) {
    int row = blockIdx.x;
    int tid = threadIdx.x;
    __shared__ float so[D_];
    for (int e = tid; e < D_; e += 64) so[e] = g_o[(size_t)row * D_ + e];
    __syncthreads();

    float acc = bc[tid];
#pragma unroll 4
    for (int k = 0; k < D_; k++) acc = fmaf(so[k], Wc[(size_t)k * C_ + tid], acc);

    __shared__ float red[2], red2[2];
    float m = acc;
#pragma unroll
    for (int off = 16; off > 0; off >>= 1) m = fmaxf(m, __shfl_xor_sync(0xffffffffu, m, off));
    if ((tid & 31) == 0) red[tid >> 5] = m;
    __syncthreads();
    m = fmaxf(red[0], red[1]);

    float e = expf(acc - m);
    float s = e;
#pragma unroll
    for (int off = 16; off > 0; off >>= 1) s += __shfl_xor_sync(0xffffffffu, s, off);
    if ((tid & 31) == 0) red2[tid >> 5] = s;
    __syncthreads();
    s = red2[0] + red2[1];

    out[(size_t)row * C_ + tid] = e / s;
}

// ---------------------------------------------------------------------------
extern "C" void kernel_launch(void* const* d_in, const int* in_sizes, int n_in,
                              void* d_out, int out_size) {
    const float* x    = (const float*)d_in[0];
    const void*  tidx = d_in[1];                 // int32 or int64 — probed on device
    const float* W1   = (const float*)d_in[2];
    const float* b1   = (const float*)d_in[3];
    const float* W2   = (const float*)d_in[4];
    const float* b2   = (const float*)d_in[5];
    const float* W3   = (const float*)d_in[6];
    const float* b3   = (const float*)d_in[7];
    const float* W4   = (const float*)d_in[8];
    const float* b4   = (const float*)d_in[9];
    const float* Wc   = (const float*)d_in[10];
    const float* bc   = (const float*)d_in[11];
    float* out = (float*)d_out;

    void *pr, *pg, *ph3, *po;
    cudaGetSymbolAddress(&pr, g_r);
    cudaGetSymbolAddress(&pg, g_g);
    cudaGetSymbolAddress(&ph3, g_h3);
    cudaGetSymbolAddress(&po, g_o);

    cudaFuncSetAttribute(gemm_fp16, cudaFuncAttributeMaxDynamicSharedMemorySize,
                         4 * STAGE_H * (int)sizeof(__half));

    // 0) probe index dtype + normalize to int32; zero accumulators
    probe_reset<<<1, 1>>>();
    probe_idx<<<120, 256>>>((const unsigned int*)tidx);
    norm_idx<<<(NIDX + 255) / 256, 256>>>((const int*)tidx);
    zero_all<<<(T_ * W_ * TWOD + 255) / 256, 256>>>();

    // 1) fp16 concat operands
    prep_a<<<(M_ * D_ + 255) / 256, 256>>>(x);
    prep_b3<<<(NP * D_ + 255) / 256, 256>>>(W1);

    // 2) P(fp16) = A3 @ B3^T  (single fp16 GEMM, K=1536, cp.async pipelined)
    gemm_fp16<<<dim3(NP / 128, M_ / 128), 256, 4 * STAGE_H * sizeof(__half)>>>();

    // 3) gather+relu+sum over k
    gather_h<<<dim3(K_ / 128, W_, T_), 128>>>(b1);

    // 4) g = r @ W2 + K_*b2        (160 x 512, K=1024, 4-way k-split)
    gemm_ks<false><<<dim3(D_ / 64, 5, 4), 256>>>(
        (const float*)pr, W2, b2, (float)K_, (float*)pg, T_ * W_, D_, TWOD);

    // 5) h3_pre = g @ W3 + b3      (160 x 1024, K=512, 4-way k-split; relu deferred)
    gemm_ks<false><<<dim3(TWOD / 64, 5, 4), 256>>>(
        (const float*)pg, W3, b3, 1.f, (float*)ph3, T_ * W_, TWOD, D_);

    // 6) o = relu(h3_pre) @ W4 + b4 (160 x 512, K=1024, relu applied on A load)
    gemm_ks<true><<<dim3(D_ / 64, 5, 4), 256>>>(
        (const float*)ph3, W4, b4, 1.f, (float*)po, T_ * W_, D_, TWOD);

    // 7) score + softmax -> out    (160 x 64)
    score_softmax<<<T_ * W_, 64>>>(Wc, bc, out);
}

// round 9
// speedup vs baseline: 2.2493x; 1.3541x over previous
#include <cuda_runtime.h>
#include <cuda_fp16.h>
#include <mma.h>
#include <cstdint>

using namespace nvcuda;

#define T_ 16
#define S_ 16
#define W_ 10
#define D_ 512
#define C_ 64
#define K_ 512
#define SW 160        // S_*W_
#define TWOD 1024
#define NP 3072       // 3 * TWOD
#define NIDX (T_ * W_ * 3 * K_)   // 245760 indices
#define M_ (T_ * SW)              // 2560 rows of P

// ---------------------------------------------------------------------------
// Device globals (no allocation allowed)
__device__ __half g_Ah[(size_t)M_ * D_];  // [2560][512] fp16 A
__device__ __half g_Bh[(size_t)NP * D_];  // [3072][512] fp16 B^T
__device__ __half g_Ph[(size_t)M_ * NP];  // P in fp16  [2560][3072]
__device__ float g_r[T_ * W_ * TWOD];     // 160 x 1024  sum_k relu(z)
__device__ float g_g[T_ * W_ * D_];       // 160 x 512
__device__ float g_h3[T_ * W_ * TWOD];    // 160 x 1024 (pre-relu)
__device__ float g_o[T_ * W_ * D_];       // 160 x 512
__device__ int   g_idx[NIDX];             // normalized int32 indices
__device__ unsigned int g_oddor;          // dtype probe result

// ---------------------------------------------------------------------------
__device__ __forceinline__ void cp_async16(void* dst, const void* src) {
    uint32_t d;
    asm("{ .reg .u64 t; cvta.to.shared.u64 t, %1; cvt.u32.u64 %0, t; }" : "=r"(d) : "l"(dst));
    asm volatile("cp.async.cg.shared.global [%0], [%1], 16;" :: "r"(d), "l"(src));
}

// ---------------------------------------------------------------------------
// dtype probe + index normalization (int64 vs int32 robustness)
__global__ void probe_reset() { g_oddor = 0u; }

__global__ void probe_idx(const unsigned int* __restrict__ raw) {
    unsigned int v = 0;
    for (int i = blockIdx.x * 256 + threadIdx.x; i < NIDX / 2; i += gridDim.x * 256)
        v |= raw[2 * i + 1];
#pragma unroll
    for (int off = 16; off > 0; off >>= 1) v |= __shfl_xor_sync(0xffffffffu, v, off);
    if ((threadIdx.x & 31) == 0 && v) atomicOr(&g_oddor, v);
}

__global__ void norm_idx(const int* __restrict__ raw) {
    int i = blockIdx.x * 256 + threadIdx.x;
    if (i >= NIDX) return;
    int v = (g_oddor != 0u) ? raw[i] : raw[2 * i];
    v = min(max(v, 0), SW - 1);
    g_idx[i] = v;
}

// ---------------------------------------------------------------------------
// X (2560x512 fp32) -> fp16 A [2560][512], vectorized (float4 in, uint2 out)
__global__ void prep_a(const float* __restrict__ x) {
    int i = blockIdx.x * 256 + threadIdx.x;     // i indexes groups of 4 elements
    if (i >= M_ * D_ / 4) return;
    float4 v = *(const float4*)(x + (size_t)i * 4);
    __half2 h0 = __floats2half2_rn(v.x, v.y);
    __half2 h1 = __floats2half2_rn(v.z, v.w);
    uint2 o = {*(uint32_t*)&h0, *(uint32_t*)&h1};
    *(uint2*)(g_Ah + (size_t)i * 4) = o;
}

// W1 (1536 x 1024) -> fp16 B^T [3072][512]: B^T[n][k] = W1[s*512+k][o], n=s*1024+o
__global__ void prep_b(const float* __restrict__ W1) {
    int i = blockIdx.x * 256 + threadIdx.x;
    if (i >= NP * D_) return;
    int n = i >> 9, k = i & 511;
    int s = n >> 10, o = n & 1023;
    g_Bh[i] = __float2half_rn(W1[(size_t)(s * D_ + k) * TWOD + o]);
}

// ---------------------------------------------------------------------------
// fp16 GEMM, fp32 accum: P(fp16 2560x3072) = A (2560x512) @ B^T (3072x512)
// CTA 128x128, 8 warps (warp tile 32x64), BK=64, 2-stage cp.async pipeline.
#define BK 64
#define KPAD 72
#define STAGE_H (128 * KPAD)         // halves per matrix per stage (9216)
#define NCH (D_ / BK)                // 8 chunks

__global__ __launch_bounds__(256, 1) void gemm_fp16() {
    extern __shared__ __half sh[];   // [2 stages][A 128x72 | B 128x72]

    int tid = threadIdx.x;
    int wid = tid >> 5, lane = tid & 31;
    int warp_m = wid & 3;    // 4 warps along M -> 32 rows each
    int warp_n = wid >> 2;   // 2 warps along N -> 64 cols each
    int row0 = blockIdx.y * 128;
    int col0 = blockIdx.x * 128;

    wmma::fragment<wmma::accumulator, 16, 16, 16, float> acc[2][4];
#pragma unroll
    for (int i = 0; i < 2; i++)
#pragma unroll
        for (int j = 0; j < 4; j++) wmma::fill_fragment(acc[i][j], 0.f);

    auto prefetch = [&](int c) {
        __half* As = sh + (c & 1) * (2 * STAGE_H);
        __half* Bs = As + STAGE_H;
        int k0 = c * BK;
#pragma unroll
        for (int j = 0; j < 4; j++) {
            int idx = tid + j * 256;
            int r = idx >> 3, q = (idx & 7) * 8;
            cp_async16(&As[r * KPAD + q], g_Ah + (size_t)(row0 + r) * D_ + k0 + q);
            cp_async16(&Bs[r * KPAD + q], g_Bh + (size_t)(col0 + r) * D_ + k0 + q);
        }
        asm volatile("cp.async.commit_group;" ::: "memory");
    };

    prefetch(0);
    for (int c = 0; c < NCH; c++) {
        if (c + 1 < NCH) {
            prefetch(c + 1);
            asm volatile("cp.async.wait_group 1;" ::: "memory");
        } else {
            asm volatile("cp.async.wait_group 0;" ::: "memory");
        }
        __syncthreads();

        const __half* As = sh + (c & 1) * (2 * STAGE_H);
        const __half* Bs = As + STAGE_H;
#pragma unroll
        for (int kk = 0; kk < BK; kk += 16) {
            wmma::fragment<wmma::matrix_a, 16, 16, 16, __half, wmma::row_major> fa[2];
            wmma::fragment<wmma::matrix_b, 16, 16, 16, __half, wmma::col_major> fb[4];
#pragma unroll
            for (int i = 0; i < 2; i++)
                wmma::load_matrix_sync(fa[i], As + (warp_m * 32 + i * 16) * KPAD + kk, KPAD);
#pragma unroll
            for (int j = 0; j < 4; j++)
                wmma::load_matrix_sync(fb[j], Bs + (warp_n * 64 + j * 16) * KPAD + kk, KPAD);
#pragma unroll
            for (int i = 0; i < 2; i++)
#pragma unroll
                for (int j = 0; j < 4; j++)
                    wmma::mma_sync(acc[i][j], fa[i], fb[j], acc[i][j]);
        }
        __syncthreads();
    }

    // Epilogue: per-warp 16x16 float patch in smem, convert to fp16, store P.
    float* patch = (float*)sh + wid * 256;
#pragma unroll
    for (int i = 0; i < 2; i++)
#pragma unroll
        for (int j = 0; j < 4; j++) {
            wmma::store_matrix_sync(patch, acc[i][j], 16, wmma::mem_row_major);
            __syncwarp();
            int m = row0 + warp_m * 32 + i * 16;
            int n = col0 + warp_n * 64 + j * 16;
            int pr = lane >> 1, pc = (lane & 1) * 8;
            __half2 o[4];
#pragma unroll
            for (int e = 0; e < 4; e++)
                o[e] = __floats2half2_rn(patch[pr * 16 + pc + 2 * e],
                                         patch[pr * 16 + pc + 2 * e + 1]);
            *(uint4*)(g_Ph + (size_t)(m + pr) * NP + n + pc) = *(uint4*)o;
            __syncwarp();
        }
}

// ---------------------------------------------------------------------------
// Zero all accumulator buffers (r, g, h3, o) in one pass.
__global__ void zero_all() {
    int idx = blockIdx.x * 256 + threadIdx.x;
    if (idx < T_ * W_ * TWOD) g_r[idx] = 0.f;
    if (idx < T_ * W_ * TWOD) g_h3[idx] = 0.f;
    if (idx < T_ * W_ * D_) { g_g[idx] = 0.f; g_o[idx] = 0.f; }
}

// ---------------------------------------------------------------------------
// Gather + relu + k-accumulate on fp16 P. grid (K_/128, W_, T_), 128 threads x 8 cols.
__global__ __launch_bounds__(128) void gather_h(const float* __restrict__ b1) {
    int t = blockIdx.z, w = blockIdx.y, kc = blockIdx.x;
    __shared__ int sidx[3][128];
    int tid = threadIdx.x;
    for (int e = tid; e < 3 * 128; e += 128) {
        int slot = e >> 7, k = e & 127;
        sidx[slot][k] = g_idx[((t * W_ + w) * 3 + slot) * K_ + kc * 128 + k];
    }
    __syncthreads();

    int col = tid * 8;
    float bb[8];
#pragma unroll
    for (int j = 0; j < 8; j++) bb[j] = b1[col + j];
    float acc[8] = {0.f, 0.f, 0.f, 0.f, 0.f, 0.f, 0.f, 0.f};
    const __half* Pt = g_Ph + (size_t)t * SW * NP;

#pragma unroll 2
    for (int k = 0; k < 128; k++) {
        uint4 va = *(const uint4*)(Pt + (size_t)sidx[0][k] * NP + col);
        uint4 vb = *(const uint4*)(Pt + (size_t)sidx[1][k] * NP + 1024 + col);
        uint4 vc = *(const uint4*)(Pt + (size_t)sidx[2][k] * NP + 2048 + col);
        const __half2* ha = (const __half2*)&va;
        const __half2* hb = (const __half2*)&vb;
        const __half2* hc = (const __half2*)&vc;
#pragma unroll
        for (int j = 0; j < 4; j++) {
            float2 fa = __half22float2(ha[j]);
            float2 fb = __half22float2(hb[j]);
            float2 fc = __half22float2(hc[j]);
            float z0 = fa.x + fb.x + fc.x + bb[2 * j];
            float z1 = fa.y + fb.y + fc.y + bb[2 * j + 1];
            acc[2 * j]     += fmaxf(z0, 0.f);
            acc[2 * j + 1] += fmaxf(z1, 0.f);
        }
    }
    float* rp = g_r + (size_t)(t * W_ + w) * TWOD + col;
#pragma unroll
    for (int j = 0; j < 8; j++) atomicAdd(rp + j, acc[j]);
}

// ---------------------------------------------------------------------------
// Small-M k-split GEMM: Cm += A[k-slice] @ B[k-slice] (atomicAdd), bias from z==0.
// RELUA applies relu to A elements on load. BM=32, BN=64, BK=16, 256 threads.
template <bool RELUA>
__global__ __launch_bounds__(256) void gemm_ks(const float* __restrict__ A,
                                               const float* __restrict__ B,
                                               const float* __restrict__ bias,
                                               float bscale,
                                               float* __restrict__ Cm,
                                               int M, int N, int Kd) {
    __shared__ float As[16][33];
    __shared__ float Bs[16][64];
    int col0 = blockIdx.x * 64;
    int row0 = blockIdx.y * 32;
    int tid = threadIdx.x;
    int tx = tid & 15, ty = tid >> 4;
    int klen = Kd / gridDim.z;
    int kbeg = blockIdx.z * klen, kend = kbeg + klen;
    float acc[2][4] = {};

    for (int k0 = kbeg; k0 < kend; k0 += 16) {
#pragma unroll
        for (int l = 0; l < 2; l++) {
            int e = tid + l * 256;
            int m = e >> 4, kk = e & 15;
            float v = A[(size_t)(row0 + m) * Kd + k0 + kk];
            if (RELUA) v = fmaxf(v, 0.f);
            As[kk][m] = v;
        }
        {
            int kk = tid >> 4, c = (tid & 15) * 4;
            *(float4*)&Bs[kk][c] = *(const float4*)(B + (size_t)(k0 + kk) * N + col0 + c);
        }
        __syncthreads();
#pragma unroll
        for (int kk = 0; kk < 16; kk++) {
            float a0 = As[kk][ty * 2], a1 = As[kk][ty * 2 + 1];
            float4 b = *(const float4*)&Bs[kk][tx * 4];
            acc[0][0] = fmaf(a0, b.x, acc[0][0]);
            acc[0][1] = fmaf(a0, b.y, acc[0][1]);
            acc[0][2] = fmaf(a0, b.z, acc[0][2]);
            acc[0][3] = fmaf(a0, b.w, acc[0][3]);
            acc[1][0] = fmaf(a1, b.x, acc[1][0]);
            acc[1][1] = fmaf(a1, b.y, acc[1][1]);
            acc[1][2] = fmaf(a1, b.z, acc[1][2]);
            acc[1][3] = fmaf(a1, b.w, acc[1][3]);
        }
        __syncthreads();
    }
#pragma unroll
    for (int i = 0; i < 2; i++) {
        int row = row0 + ty * 2 + i;
#pragma unroll
        for (int j = 0; j < 4; j++) {
            int colx = col0 + tx * 4 + j;
            float v = acc[i][j];
            if (blockIdx.z == 0) v += bias[colx] * bscale;
            atomicAdd(&Cm[(size_t)row * N + colx], v);
        }
    }
}

// ---------------------------------------------------------------------------
// score = o @ Wc + bc, softmax over C_=64. One block (64 threads) per row.
__global__ __launch_bounds__(64) void score_softmax(const float* __restrict__ Wc,
                                                    const float* __restrict__ bc,
                                                    float* __restrict__ out) {
    int row = blockIdx.x;
    int tid = threadIdx.x;
    __shared__ float so[D_];
    for (int e = tid; e < D_; e += 64) so[e] = g_o[(size_t)row * D_ + e];
    __syncthreads();

    float acc = bc[tid];
#pragma unroll 4
    for (int k = 0; k < D_; k++) acc = fmaf(so[k], Wc[(size_t)k * C_ + tid], acc);

    __shared__ float red[2], red2[2];
    float m = acc;
#pragma unroll
    for (int off = 16; off > 0; off >>= 1) m = fmaxf(m, __shfl_xor_sync(0xffffffffu, m, off));
    if ((tid & 31) == 0) red[tid >> 5] = m;
    __syncthreads();
    m = fmaxf(red[0], red[1]);

    float e = expf(acc - m);
    float s = e;
#pragma unroll
    for (int off = 16; off > 0; off >>= 1) s += __shfl_xor_sync(0xffffffffu, s, off);
    if ((tid & 31) == 0) red2[tid >> 5] = s;
    __syncthreads();
    s = red2[0] + red2[1];

    out[(size_t)row * C_ + tid] = e / s;
}

// ---------------------------------------------------------------------------
extern "C" void kernel_launch(void* const* d_in, const int* in_sizes, int n_in,
                              void* d_out, int out_size) {
    const float* x    = (const float*)d_in[0];
    const void*  tidx = d_in[1];                 // int32 or int64 — probed on device
    const float* W1   = (const float*)d_in[2];
    const float* b1   = (const float*)d_in[3];
    const float* W2   = (const float*)d_in[4];
    const float* b2   = (const float*)d_in[5];
    const float* W3   = (const float*)d_in[6];
    const float* b3   = (const float*)d_in[7];
    const float* W4   = (const float*)d_in[8];
    const float* b4   = (const float*)d_in[9];
    const float* Wc   = (const float*)d_in[10];
    const float* bc   = (const float*)d_in[11];
    float* out = (float*)d_out;

    void *pr, *pg, *ph3, *po;
    cudaGetSymbolAddress(&pr, g_r);
    cudaGetSymbolAddress(&pg, g_g);
    cudaGetSymbolAddress(&ph3, g_h3);
    cudaGetSymbolAddress(&po, g_o);

    cudaFuncSetAttribute(gemm_fp16, cudaFuncAttributeMaxDynamicSharedMemorySize,
                         4 * STAGE_H * (int)sizeof(__half));

    // 0) probe index dtype + normalize to int32; zero accumulators
    probe_reset<<<1, 1>>>();
    probe_idx<<<120, 256>>>((const unsigned int*)tidx);
    norm_idx<<<(NIDX + 255) / 256, 256>>>((const int*)tidx);
    zero_all<<<(T_ * W_ * TWOD + 255) / 256, 256>>>();

    // 1) fp16 operands (direct convert — no split, no concat)
    prep_a<<<(M_ * D_ / 4 + 255) / 256, 256>>>(x);
    prep_b<<<(NP * D_ + 255) / 256, 256>>>(W1);

    // 2) P(fp16) = A @ B^T  (single fp16 GEMM, K=512, cp.async pipelined)
    gemm_fp16<<<dim3(NP / 128, M_ / 128), 256, 4 * STAGE_H * sizeof(__half)>>>();

    // 3) gather+relu+sum over k
    gather_h<<<dim3(K_ / 128, W_, T_), 128>>>(b1);

    // 4) g = r @ W2 + K_*b2        (160 x 512, K=1024, 4-way k-split)
    gemm_ks<false><<<dim3(D_ / 64, 5, 4), 256>>>(
        (const float*)pr, W2, b2, (float)K_, (float*)pg, T_ * W_, D_, TWOD);

    // 5) h3_pre = g @ W3 + b3      (160 x 1024, K=512, 4-way k-split; relu deferred)
    gemm_ks<false><<<dim3(TWOD / 64, 5, 4), 256>>>(
        (const float*)pg, W3, b3, 1.f, (float*)ph3, T_ * W_, TWOD, D_);

    // 6) o = relu(h3_pre) @ W4 + b4 (160 x 512, K=1024, relu applied on A load)
    gemm_ks<true><<<dim3(D_ / 64, 5, 4), 256>>>(
        (const float*)ph3, W4, b4, 1.f, (float*)po, T_ * W_, D_, TWOD);

    // 7) score + softmax -> out    (160 x 64)
    score_softmax<<<T_ * W_, 64>>>(Wc, bc, out);
}

// round 10
// speedup vs baseline: 2.2740x; 1.0110x over previous
#include <cuda_runtime.h>
#include <cuda_fp16.h>
#include <mma.h>
#include <cstdint>

using namespace nvcuda;

#define T_ 16
#define S_ 16
#define W_ 10
#define D_ 512
#define C_ 64
#define K_ 512
#define SW 160        // S_*W_
#define TWOD 1024
#define NP 3072       // 3 * TWOD
#define NIDX (T_ * W_ * 3 * K_)   // 245760 indices
#define M_ (T_ * SW)              // 2560 rows of P

// ---------------------------------------------------------------------------
// Device globals (no allocation allowed)
__device__ __half g_Ah[(size_t)M_ * D_];  // [2560][512] fp16 A
__device__ __half g_Bh[(size_t)NP * D_];  // [3072][512] fp16 B^T
__device__ __half g_Ph[(size_t)M_ * NP];  // P in fp16  [2560][3072]
__device__ float g_r[T_ * W_ * TWOD];     // 160 x 1024  sum_k relu(z)
__device__ float g_g[T_ * W_ * D_];       // 160 x 512
__device__ float g_h3[T_ * W_ * TWOD];    // 160 x 1024 (pre-relu)
__device__ float g_o[T_ * W_ * D_];       // 160 x 512
__device__ int   g_idx[NIDX];             // normalized int32 indices
__device__ unsigned int g_oddor;          // dtype probe result

// ---------------------------------------------------------------------------
__device__ __forceinline__ void cp_async16(void* dst, const void* src) {
    uint32_t d;
    asm("{ .reg .u64 t; cvta.to.shared.u64 t, %1; cvt.u32.u64 %0, t; }" : "=r"(d) : "l"(dst));
    asm volatile("cp.async.cg.shared.global [%0], [%1], 16;" :: "r"(d), "l"(src));
}

// ---------------------------------------------------------------------------
// dtype probe + index normalization (int64 vs int32 robustness)
__global__ void probe_reset() { g_oddor = 0u; }

__global__ void probe_idx(const unsigned int* __restrict__ raw) {
    unsigned int v = 0;
    for (int i = blockIdx.x * 256 + threadIdx.x; i < NIDX / 2; i += gridDim.x * 256)
        v |= raw[2 * i + 1];
#pragma unroll
    for (int off = 16; off > 0; off >>= 1) v |= __shfl_xor_sync(0xffffffffu, v, off);
    if ((threadIdx.x & 31) == 0 && v) atomicOr(&g_oddor, v);
}

__global__ void norm_idx(const int* __restrict__ raw) {
    int i = blockIdx.x * 256 + threadIdx.x;
    if (i >= NIDX) return;
    int v = (g_oddor != 0u) ? raw[i] : raw[2 * i];
    v = min(max(v, 0), SW - 1);
    g_idx[i] = v;
}

// ---------------------------------------------------------------------------
// X (2560x512 fp32) -> fp16 A [2560][512], vectorized (float4 in, uint2 out)
__global__ void prep_a(const float* __restrict__ x) {
    int i = blockIdx.x * 256 + threadIdx.x;     // i indexes groups of 4 elements
    if (i >= M_ * D_ / 4) return;
    float4 v = *(const float4*)(x + (size_t)i * 4);
    __half2 h0 = __floats2half2_rn(v.x, v.y);
    __half2 h1 = __floats2half2_rn(v.z, v.w);
    uint2 o = {*(uint32_t*)&h0, *(uint32_t*)&h1};
    *(uint2*)(g_Ah + (size_t)i * 4) = o;
}

// W1 (1536 x 1024) -> fp16 B^T [3072][512]: B^T[n][k] = W1[s*512+k][o], n=s*1024+o
__global__ void prep_b(const float* __restrict__ W1) {
    int i = blockIdx.x * 256 + threadIdx.x;
    if (i >= NP * D_) return;
    int n = i >> 9, k = i & 511;
    int s = n >> 10, o = n & 1023;
    g_Bh[i] = __float2half_rn(W1[(size_t)(s * D_ + k) * TWOD + o]);
}

// ---------------------------------------------------------------------------
// fp16 GEMM, fp32 accum: P(fp16 2560x3072) = A (2560x512) @ B^T (3072x512)
// CTA 128x128, 8 warps (warp tile 32x64), BK=64, 2-stage cp.async pipeline.
#define BK 64
#define KPAD 72
#define STAGE_H (128 * KPAD)         // halves per matrix per stage (9216)
#define NCH (D_ / BK)                // 8 chunks

__global__ __launch_bounds__(256, 1) void gemm_fp16() {
    extern __shared__ __half sh[];   // [2 stages][A 128x72 | B 128x72]

    int tid = threadIdx.x;
    int wid = tid >> 5, lane = tid & 31;
    int warp_m = wid & 3;    // 4 warps along M -> 32 rows each
    int warp_n = wid >> 2;   // 2 warps along N -> 64 cols each
    int row0 = blockIdx.y * 128;
    int col0 = blockIdx.x * 128;

    wmma::fragment<wmma::accumulator, 16, 16, 16, float> acc[2][4];
#pragma unroll
    for (int i = 0; i < 2; i++)
#pragma unroll
        for (int j = 0; j < 4; j++) wmma::fill_fragment(acc[i][j], 0.f);

    auto prefetch = [&](int c) {
        __half* As = sh + (c & 1) * (2 * STAGE_H);
        __half* Bs = As + STAGE_H;
        int k0 = c * BK;
#pragma unroll
        for (int j = 0; j < 4; j++) {
            int idx = tid + j * 256;
            int r = idx >> 3, q = (idx & 7) * 8;
            cp_async16(&As[r * KPAD + q], g_Ah + (size_t)(row0 + r) * D_ + k0 + q);
            cp_async16(&Bs[r * KPAD + q], g_Bh + (size_t)(col0 + r) * D_ + k0 + q);
        }
        asm volatile("cp.async.commit_group;" ::: "memory");
    };

    prefetch(0);
    for (int c = 0; c < NCH; c++) {
        if (c + 1 < NCH) {
            prefetch(c + 1);
            asm volatile("cp.async.wait_group 1;" ::: "memory");
        } else {
            asm volatile("cp.async.wait_group 0;" ::: "memory");
        }
        __syncthreads();

        const __half* As = sh + (c & 1) * (2 * STAGE_H);
        const __half* Bs = As + STAGE_H;
#pragma unroll
        for (int kk = 0; kk < BK; kk += 16) {
            wmma::fragment<wmma::matrix_a, 16, 16, 16, __half, wmma::row_major> fa[2];
            wmma::fragment<wmma::matrix_b, 16, 16, 16, __half, wmma::col_major> fb[4];
#pragma unroll
            for (int i = 0; i < 2; i++)
                wmma::load_matrix_sync(fa[i], As + (warp_m * 32 + i * 16) * KPAD + kk, KPAD);
#pragma unroll
            for (int j = 0; j < 4; j++)
                wmma::load_matrix_sync(fb[j], Bs + (warp_n * 64 + j * 16) * KPAD + kk, KPAD);
#pragma unroll
            for (int i = 0; i < 2; i++)
#pragma unroll
                for (int j = 0; j < 4; j++)
                    wmma::mma_sync(acc[i][j], fa[i], fb[j], acc[i][j]);
        }
        __syncthreads();
    }

    // Epilogue: per-warp 16x16 float patch in smem, convert to fp16, store P.
    float* patch = (float*)sh + wid * 256;
#pragma unroll
    for (int i = 0; i < 2; i++)
#pragma unroll
        for (int j = 0; j < 4; j++) {
            wmma::store_matrix_sync(patch, acc[i][j], 16, wmma::mem_row_major);
            __syncwarp();
            int m = row0 + warp_m * 32 + i * 16;
            int n = col0 + warp_n * 64 + j * 16;
            int pr = lane >> 1, pc = (lane & 1) * 8;
            __half2 o[4];
#pragma unroll
            for (int e = 0; e < 4; e++)
                o[e] = __floats2half2_rn(patch[pr * 16 + pc + 2 * e],
                                         patch[pr * 16 + pc + 2 * e + 1]);
            *(uint4*)(g_Ph + (size_t)(m + pr) * NP + n + pc) = *(uint4*)o;
            __syncwarp();
        }
}

// ---------------------------------------------------------------------------
// Zero k-split accumulator buffers (g, h3, o). r is plain-stored now.
__global__ void zero_gho() {
    int idx = blockIdx.x * 256 + threadIdx.x;
    if (idx < T_ * W_ * TWOD) g_h3[idx] = 0.f;
    if (idx < T_ * W_ * D_) { g_g[idx] = 0.f; g_o[idx] = 0.f; }
}

// ---------------------------------------------------------------------------
// Smem-staged gather: block = (chunk, t). Stages Ps[3][160][128] (123KB) once,
// serves all w,k row-reads from smem. 256 threads = 16 col-slots x 16 k-groups.
// Writes g_r directly (block owns the full k-sum) — no atomics.
#define GCW 128
#define PS_HALVES (3 * SW * GCW)               // 61440 halves
#define GSM_BYTES (PS_HALVES * 2 + 3 * K_ * 4 + 16 * GCW * 4)  // 137216

__global__ __launch_bounds__(256, 1) void gather_s(const float* __restrict__ b1) {
    extern __shared__ char gsm[];
    __half* Ps  = (__half*)gsm;                              // [3][160][128]
    int*   sidx = (int*)(gsm + PS_HALVES * 2);               // [3][512]
    float* part = (float*)(gsm + PS_HALVES * 2 + 3 * K_ * 4); // [16][128]

    int chunk = blockIdx.x;   // 0..7 (128-col chunks of the 1024-wide output)
    int t     = blockIdx.y;   // 0..15
    int tid = threadIdx.x;

    // Stage P slice: slot s, row n, cols [s*1024 + chunk*128, +128)
    const __half* Pt = g_Ph + (size_t)t * SW * NP;
    for (int i = tid; i < PS_HALVES / 8; i += 256) {   // 7680 uint4
        int q = i & 15;                // uint4 within row
        int r = (i >> 4) % SW;
        int s = i / (16 * SW);
        *(uint4*)(Ps + (s * SW + r) * GCW + q * 8) =
            *(const uint4*)(Pt + (size_t)r * NP + s * 1024 + chunk * GCW + q * 8);
    }

    int cs = (tid & 15) * 8;          // col-slot: 8 halves
    int kg = tid >> 4;                // k-group: 32 k each
    int col = chunk * GCW + cs;
    float bb[8];
#pragma unroll
    for (int j = 0; j < 8; j++) bb[j] = b1[col + j];

    for (int w = 0; w < W_; w++) {
        __syncthreads();   // staging done (w=0) / part+sidx consumers done (w>0)
        for (int i = tid; i < 3 * K_; i += 256)
            sidx[i] = g_idx[(t * W_ + w) * 3 * K_ + i];
        __syncthreads();

        float acc[8] = {};
#pragma unroll 4
        for (int k = kg * 32; k < kg * 32 + 32; k++) {
            int a = sidx[k];
            int b = sidx[K_ + k];
            int c = sidx[2 * K_ + k];
            uint4 va = *(uint4*)(Ps + (size_t)a * GCW + cs);
            uint4 vb = *(uint4*)(Ps + (SW + (size_t)b) * GCW + cs);
            uint4 vc = *(uint4*)(Ps + (2 * SW + (size_t)c) * GCW + cs);
            const __half2* ha = (const __half2*)&va;
            const __half2* hb = (const __half2*)&vb;
            const __half2* hc = (const __half2*)&vc;
#pragma unroll
            for (int j = 0; j < 4; j++) {
                float2 fa = __half22float2(ha[j]);
                float2 fb = __half22float2(hb[j]);
                float2 fc = __half22float2(hc[j]);
                float z0 = fa.x + fb.x + fc.x + bb[2 * j];
                float z1 = fa.y + fb.y + fc.y + bb[2 * j + 1];
                acc[2 * j]     += fmaxf(z0, 0.f);
                acc[2 * j + 1] += fmaxf(z1, 0.f);
            }
        }
        // partials -> smem, tree-reduce across the 16 k-groups
#pragma unroll
        for (int j = 0; j < 4; j++)
            *(float2*)&part[kg * GCW + cs + 2 * j] = make_float2(acc[2 * j], acc[2 * j + 1]);
        __syncthreads();
        if (tid < GCW) {
            float s = 0.f;
#pragma unroll
            for (int g = 0; g < 16; g++) s += part[g * GCW + tid];
            g_r[(size_t)(t * W_ + w) * TWOD + chunk * GCW + tid] = s;
        }
    }
}

// ---------------------------------------------------------------------------
// Small-M k-split GEMM: Cm += A[k-slice] @ B[k-slice] (atomicAdd), bias from z==0.
// RELUA applies relu to A elements on load. BM=32, BN=64, BK=16, 256 threads.
template <bool RELUA>
__global__ __launch_bounds__(256) void gemm_ks(const float* __restrict__ A,
                                               const float* __restrict__ B,
                                               const float* __restrict__ bias,
                                               float bscale,
                                               float* __restrict__ Cm,
                                               int M, int N, int Kd) {
    __shared__ float As[16][33];
    __shared__ float Bs[16][64];
    int col0 = blockIdx.x * 64;
    int row0 = blockIdx.y * 32;
    int tid = threadIdx.x;
    int tx = tid & 15, ty = tid >> 4;
    int klen = Kd / gridDim.z;
    int kbeg = blockIdx.z * klen, kend = kbeg + klen;
    float acc[2][4] = {};

    for (int k0 = kbeg; k0 < kend; k0 += 16) {
#pragma unroll
        for (int l = 0; l < 2; l++) {
            int e = tid + l * 256;
            int m = e >> 4, kk = e & 15;
            float v = A[(size_t)(row0 + m) * Kd + k0 + kk];
            if (RELUA) v = fmaxf(v, 0.f);
            As[kk][m] = v;
        }
        {
            int kk = tid >> 4, c = (tid & 15) * 4;
            *(float4*)&Bs[kk][c] = *(const float4*)(B + (size_t)(k0 + kk) * N + col0 + c);
        }
        __syncthreads();
#pragma unroll
        for (int kk = 0; kk < 16; kk++) {
            float a0 = As[kk][ty * 2], a1 = As[kk][ty * 2 + 1];
            float4 b = *(const float4*)&Bs[kk][tx * 4];
            acc[0][0] = fmaf(a0, b.x, acc[0][0]);
            acc[0][1] = fmaf(a0, b.y, acc[0][1]);
            acc[0][2] = fmaf(a0, b.z, acc[0][2]);
            acc[0][3] = fmaf(a0, b.w, acc[0][3]);
            acc[1][0] = fmaf(a1, b.x, acc[1][0]);
            acc[1][1] = fmaf(a1, b.y, acc[1][1]);
            acc[1][2] = fmaf(a1, b.z, acc[1][2]);
            acc[1][3] = fmaf(a1, b.w, acc[1][3]);
        }
        __syncthreads();
    }
#pragma unroll
    for (int i = 0; i < 2; i++) {
        int row = row0 + ty * 2 + i;
#pragma unroll
        for (int j = 0; j < 4; j++) {
            int colx = col0 + tx * 4 + j;
            float v = acc[i][j];
            if (blockIdx.z == 0) v += bias[colx] * bscale;
            atomicAdd(&Cm[(size_t)row * N + colx], v);
        }
    }
}

// ---------------------------------------------------------------------------
// score = o @ Wc + bc, softmax over C_=64. One block (64 threads) per row.
__global__ __launch_bounds__(64) void score_softmax(const float* __restrict__ Wc,
                                                    const float* __restrict__ bc,
                                                    float* __restrict__ out) {
    int row = blockIdx.x;
    int tid = threadIdx.x;
    __shared__ float so[D_];
    for (int e = tid; e < D_; e += 64) so[e] = g_o[(size_t)row * D_ + e];
    __syncthreads();

    float acc = bc[tid];
#pragma unroll 4
    for (int k = 0; k < D_; k++) acc = fmaf(so[k], Wc[(size_t)k * C_ + tid], acc);

    __shared__ float red[2], red2[2];
    float m = acc;
#pragma unroll
    for (int off = 16; off > 0; off >>= 1) m = fmaxf(m, __shfl_xor_sync(0xffffffffu, m, off));
    if ((tid & 31) == 0) red[tid >> 5] = m;
    __syncthreads();
    m = fmaxf(red[0], red[1]);

    float e = expf(acc - m);
    float s = e;
#pragma unroll
    for (int off = 16; off > 0; off >>= 1) s += __shfl_xor_sync(0xffffffffu, s, off);
    if ((tid & 31) == 0) red2[tid >> 5] = s;
    __syncthreads();
    s = red2[0] + red2[1];

    out[(size_t)row * C_ + tid] = e / s;
}

// ---------------------------------------------------------------------------
extern "C" void kernel_launch(void* const* d_in, const int* in_sizes, int n_in,
                              void* d_out, int out_size) {
    const float* x    = (const float*)d_in[0];
    const void*  tidx = d_in[1];                 // int32 or int64 — probed on device
    const float* W1   = (const float*)d_in[2];
    const float* b1   = (const float*)d_in[3];
    const float* W2   = (const float*)d_in[4];
    const float* b2   = (const float*)d_in[5];
    const float* W3   = (const float*)d_in[6];
    const float* b3   = (const float*)d_in[7];
    const float* W4   = (const float*)d_in[8];
    const float* b4   = (const float*)d_in[9];
    const float* Wc   = (const float*)d_in[10];
    const float* bc   = (const float*)d_in[11];
    float* out = (float*)d_out;

    void *pr, *pg, *ph3, *po;
    cudaGetSymbolAddress(&pr, g_r);
    cudaGetSymbolAddress(&pg, g_g);
    cudaGetSymbolAddress(&ph3, g_h3);
    cudaGetSymbolAddress(&po, g_o);

    cudaFuncSetAttribute(gemm_fp16, cudaFuncAttributeMaxDynamicSharedMemorySize,
                         4 * STAGE_H * (int)sizeof(__half));
    cudaFuncSetAttribute(gather_s, cudaFuncAttributeMaxDynamicSharedMemorySize,
                         GSM_BYTES);

    // Launches 0-4, putting gemm_fp16 at launch index 5 for ncu (-s 5 -c 1).
    probe_reset<<<1, 1>>>();
    probe_idx<<<120, 256>>>((const unsigned int*)tidx);
    norm_idx<<<(NIDX + 255) / 256, 256>>>((const int*)tidx);
    prep_a<<<(M_ * D_ / 4 + 255) / 256, 256>>>(x);
    prep_b<<<(NP * D_ + 255) / 256, 256>>>(W1);

    // 5) P(fp16) = A @ B^T  (single fp16 GEMM, K=512, cp.async pipelined)
    gemm_fp16<<<dim3(NP / 128, M_ / 128), 256, 4 * STAGE_H * sizeof(__half)>>>();

    // 6) zero k-split accumulators (g, h3, o)
    zero_gho<<<(T_ * W_ * TWOD + 255) / 256, 256>>>();

    // 7) smem-staged gather+relu+k-sum -> r (direct store)
    gather_s<<<dim3(TWOD / GCW, T_), 256, GSM_BYTES>>>(b1);

    // 8) g = r @ W2 + K_*b2        (160 x 512, K=1024, 4-way k-split)
    gemm_ks<false><<<dim3(D_ / 64, 5, 4), 256>>>(
        (const float*)pr, W2, b2, (float)K_, (float*)pg, T_ * W_, D_, TWOD);

    // 9) h3_pre = g @ W3 + b3      (160 x 1024, K=512, 4-way k-split; relu deferred)
    gemm_ks<false><<<dim3(TWOD / 64, 5, 4), 256>>>(
        (const float*)pg, W3, b3, 1.f, (float*)ph3, T_ * W_, TWOD, D_);

    // 10) o = relu(h3_pre) @ W4 + b4 (160 x 512, K=1024, relu applied on A load)
    gemm_ks<true><<<dim3(D_ / 64, 5, 4), 256>>>(
        (const float*)ph3, W4, b4, 1.f, (float*)po, T_ * W_, D_, TWOD);

    // 11) score + softmax -> out    (160 x 64)
    score_softmax<<<T_ * W_, 64>>>(Wc, bc, out);
}

// round 11
// speedup vs baseline: 2.3201x; 1.0203x over previous
#include <cuda_runtime.h>
#include <cuda_fp16.h>
#include <mma.h>
#include <cstdint>

using namespace nvcuda;

#define T_ 16
#define S_ 16
#define W_ 10
#define D_ 512
#define C_ 64
#define K_ 512
#define SW 160        // S_*W_
#define TWOD 1024
#define NP 3072       // 3 * TWOD
#define NIDX (T_ * W_ * 3 * K_)   // 245760 indices
#define M_ (T_ * SW)              // 2560 rows of P

// ---------------------------------------------------------------------------
// Device globals (no allocation allowed)
__device__ __half g_Ah[(size_t)M_ * D_];  // [2560][512] fp16 A
__device__ __half g_Bh[(size_t)NP * D_];  // [3072][512] fp16 B^T
__device__ __half g_Ph[(size_t)M_ * NP];  // P in fp16  [2560][3072]
__device__ float g_r[T_ * W_ * TWOD];     // 160 x 1024  sum_k relu(z)
__device__ float g_g[T_ * W_ * D_];       // 160 x 512
__device__ float g_h3[T_ * W_ * TWOD];    // 160 x 1024 (pre-relu)
__device__ float g_o[T_ * W_ * D_];       // 160 x 512
__device__ int   g_idx[NIDX];             // normalized int32 indices
__device__ unsigned int g_oddor;          // dtype probe result

// ---------------------------------------------------------------------------
__device__ __forceinline__ void cp_async16(void* dst, const void* src) {
    uint32_t d;
    asm("{ .reg .u64 t; cvta.to.shared.u64 t, %1; cvt.u32.u64 %0, t; }" : "=r"(d) : "l"(dst));
    asm volatile("cp.async.cg.shared.global [%0], [%1], 16;" :: "r"(d), "l"(src));
}

// ---------------------------------------------------------------------------
// dtype probe + index normalization (int64 vs int32 robustness)
__global__ void probe_reset() { g_oddor = 0u; }

__global__ void probe_idx(const unsigned int* __restrict__ raw) {
    unsigned int v = 0;
    for (int i = blockIdx.x * 256 + threadIdx.x; i < NIDX / 2; i += gridDim.x * 256)
        v |= raw[2 * i + 1];
#pragma unroll
    for (int off = 16; off > 0; off >>= 1) v |= __shfl_xor_sync(0xffffffffu, v, off);
    if ((threadIdx.x & 31) == 0 && v) atomicOr(&g_oddor, v);
}

__global__ void norm_idx(const int* __restrict__ raw) {
    int i = blockIdx.x * 256 + threadIdx.x;
    if (i >= NIDX) return;
    int v = (g_oddor != 0u) ? raw[i] : raw[2 * i];
    v = min(max(v, 0), SW - 1);
    g_idx[i] = v;
}

// ---------------------------------------------------------------------------
// X (2560x512 fp32) -> fp16 A [2560][512], vectorized (float4 in, uint2 out)
__global__ void prep_a(const float* __restrict__ x) {
    int i = blockIdx.x * 256 + threadIdx.x;     // i indexes groups of 4 elements
    if (i >= M_ * D_ / 4) return;
    float4 v = *(const float4*)(x + (size_t)i * 4);
    __half2 h0 = __floats2half2_rn(v.x, v.y);
    __half2 h1 = __floats2half2_rn(v.z, v.w);
    uint2 o = {*(uint32_t*)&h0, *(uint32_t*)&h1};
    *(uint2*)(g_Ah + (size_t)i * 4) = o;
}

// W1 (1536 x 1024) -> fp16 B^T [3072][512]: B^T[n][k] = W1[s*512+k][o], n=s*1024+o
__global__ void prep_b(const float* __restrict__ W1) {
    int i = blockIdx.x * 256 + threadIdx.x;
    if (i >= NP * D_) return;
    int n = i >> 9, k = i & 511;
    int s = n >> 10, o = n & 1023;
    g_Bh[i] = __float2half_rn(W1[(size_t)(s * D_ + k) * TWOD + o]);
}

// ---------------------------------------------------------------------------
// fp16 GEMM, fp32 accum: P(fp16 2560x3072) = A (2560x512) @ B^T (3072x512)
// CTA 128x128, 8 warps (warp tile 32x64), BK=32, 3-stage cp.async ring,
// single __syncthreads per chunk, 2 CTAs/SM (60KB smem).
#define BK 32
#define KPAD 40
#define STG (128 * KPAD)             // halves per matrix per stage (5120)
#define NSTAGE 3
#define NCH (D_ / BK)                // 16 chunks
#define GEMM_SMEM (NSTAGE * 2 * STG * 2)   // 61440 bytes

__global__ __launch_bounds__(256, 2) void gemm_fp16() {
    extern __shared__ __half sh[];   // [3 stages][A 128x40 | B 128x40]

    int tid = threadIdx.x;
    int wid = tid >> 5, lane = tid & 31;
    int warp_m = wid & 3;    // 4 warps along M -> 32 rows each
    int warp_n = wid >> 2;   // 2 warps along N -> 64 cols each
    int row0 = blockIdx.y * 128;
    int col0 = blockIdx.x * 128;

    wmma::fragment<wmma::accumulator, 16, 16, 16, float> acc[2][4];
#pragma unroll
    for (int i = 0; i < 2; i++)
#pragma unroll
        for (int j = 0; j < 4; j++) wmma::fill_fragment(acc[i][j], 0.f);

    auto prefetch = [&](int c) {
        int s = c % NSTAGE;
        __half* As = sh + s * (2 * STG);
        __half* Bs = As + STG;
        int k0 = c * BK;
#pragma unroll
        for (int j = 0; j < 2; j++) {
            int idx = tid + j * 256;
            int r = idx >> 2, q = (idx & 3) * 8;
            cp_async16(&As[r * KPAD + q], g_Ah + (size_t)(row0 + r) * D_ + k0 + q);
            cp_async16(&Bs[r * KPAD + q], g_Bh + (size_t)(col0 + r) * D_ + k0 + q);
        }
        asm volatile("cp.async.commit_group;" ::: "memory");
    };

    prefetch(0);
    prefetch(1);
    for (int c = 0; c < NCH; c++) {
        if (c < NCH - 1) {
            asm volatile("cp.async.wait_group 1;" ::: "memory");   // stage c ready
        } else {
            asm volatile("cp.async.wait_group 0;" ::: "memory");   // drain last
        }
        __syncthreads();   // stage c visible; all warps done with compute(c-1)
        if (c + 2 < NCH) prefetch(c + 2);   // writes stage (c-1)%3 — free now

        const __half* As = sh + (c % NSTAGE) * (2 * STG);
        const __half* Bs = As + STG;
#pragma unroll
        for (int kk = 0; kk < BK; kk += 16) {
            wmma::fragment<wmma::matrix_a, 16, 16, 16, __half, wmma::row_major> fa[2];
            wmma::fragment<wmma::matrix_b, 16, 16, 16, __half, wmma::col_major> fb[4];
#pragma unroll
            for (int i = 0; i < 2; i++)
                wmma::load_matrix_sync(fa[i], As + (warp_m * 32 + i * 16) * KPAD + kk, KPAD);
#pragma unroll
            for (int j = 0; j < 4; j++)
                wmma::load_matrix_sync(fb[j], Bs + (warp_n * 64 + j * 16) * KPAD + kk, KPAD);
#pragma unroll
            for (int i = 0; i < 2; i++)
#pragma unroll
                for (int j = 0; j < 4; j++)
                    wmma::mma_sync(acc[i][j], fa[i], fb[j], acc[i][j]);
        }
    }
    __syncthreads();   // all compute done before smem reuse as epilogue scratch

    // Epilogue: per-warp 16x16 float patch in smem, convert to fp16, store P.
    float* patch = (float*)sh + wid * 256;
#pragma unroll
    for (int i = 0; i < 2; i++)
#pragma unroll
        for (int j = 0; j < 4; j++) {
            wmma::store_matrix_sync(patch, acc[i][j], 16, wmma::mem_row_major);
            __syncwarp();
            int m = row0 + warp_m * 32 + i * 16;
            int n = col0 + warp_n * 64 + j * 16;
            int pr = lane >> 1, pc = (lane & 1) * 8;
            __half2 o[4];
#pragma unroll
            for (int e = 0; e < 4; e++)
                o[e] = __floats2half2_rn(patch[pr * 16 + pc + 2 * e],
                                         patch[pr * 16 + pc + 2 * e + 1]);
            *(uint4*)(g_Ph + (size_t)(m + pr) * NP + n + pc) = *(uint4*)o;
            __syncwarp();
        }
}

// ---------------------------------------------------------------------------
// Zero k-split accumulator buffers (g, h3, o). r is plain-stored now.
__global__ void zero_gho() {
    int idx = blockIdx.x * 256 + threadIdx.x;
    if (idx < T_ * W_ * TWOD) g_h3[idx] = 0.f;
    if (idx < T_ * W_ * D_) { g_g[idx] = 0.f; g_o[idx] = 0.f; }
}

// ---------------------------------------------------------------------------
// Smem-staged gather: block = (chunk, t). Stages Ps[3][160][128] (123KB) once,
// serves all w,k row-reads from smem. 256 threads = 16 col-slots x 16 k-groups.
#define GCW 128
#define PS_HALVES (3 * SW * GCW)               // 61440 halves
#define GSM_BYTES (PS_HALVES * 2 + 3 * K_ * 4 + 16 * GCW * 4)  // 137216

__global__ __launch_bounds__(256, 1) void gather_s(const float* __restrict__ b1) {
    extern __shared__ char gsm[];
    __half* Ps  = (__half*)gsm;                              // [3][160][128]
    int*   sidx = (int*)(gsm + PS_HALVES * 2);               // [3][512]
    float* part = (float*)(gsm + PS_HALVES * 2 + 3 * K_ * 4); // [16][128]

    int chunk = blockIdx.x;   // 0..7 (128-col chunks of the 1024-wide output)
    int t     = blockIdx.y;   // 0..15
    int tid = threadIdx.x;

    // Stage P slice: slot s, row n, cols [s*1024 + chunk*128, +128)
    const __half* Pt = g_Ph + (size_t)t * SW * NP;
    for (int i = tid; i < PS_HALVES / 8; i += 256) {   // 7680 uint4
        int q = i & 15;                // uint4 within row
        int r = (i >> 4) % SW;
        int s = i / (16 * SW);
        *(uint4*)(Ps + (s * SW + r) * GCW + q * 8) =
            *(const uint4*)(Pt + (size_t)r * NP + s * 1024 + chunk * GCW + q * 8);
    }

    int cs = (tid & 15) * 8;          // col-slot: 8 halves
    int kg = tid >> 4;                // k-group: 32 k each
    int col = chunk * GCW + cs;
    float bb[8];
#pragma unroll
    for (int j = 0; j < 8; j++) bb[j] = b1[col + j];

    for (int w = 0; w < W_; w++) {
        __syncthreads();   // staging done (w=0) / part+sidx consumers done (w>0)
        for (int i = tid; i < 3 * K_; i += 256)
            sidx[i] = g_idx[(t * W_ + w) * 3 * K_ + i];
        __syncthreads();

        float acc[8] = {};
#pragma unroll 4
        for (int k = kg * 32; k < kg * 32 + 32; k++) {
            int a = sidx[k];
            int b = sidx[K_ + k];
            int c = sidx[2 * K_ + k];
            uint4 va = *(uint4*)(Ps + (size_t)a * GCW + cs);
            uint4 vb = *(uint4*)(Ps + (SW + (size_t)b) * GCW + cs);
            uint4 vc = *(uint4*)(Ps + (2 * SW + (size_t)c) * GCW + cs);
            const __half2* ha = (const __half2*)&va;
            const __half2* hb = (const __half2*)&vb;
            const __half2* hc = (const __half2*)&vc;
#pragma unroll
            for (int j = 0; j < 4; j++) {
                float2 fa = __half22float2(ha[j]);
                float2 fb = __half22float2(hb[j]);
                float2 fc = __half22float2(hc[j]);
                float z0 = fa.x + fb.x + fc.x + bb[2 * j];
                float z1 = fa.y + fb.y + fc.y + bb[2 * j + 1];
                acc[2 * j]     += fmaxf(z0, 0.f);
                acc[2 * j + 1] += fmaxf(z1, 0.f);
            }
        }
        // partials -> smem, tree-reduce across the 16 k-groups
#pragma unroll
        for (int j = 0; j < 4; j++)
            *(float2*)&part[kg * GCW + cs + 2 * j] = make_float2(acc[2 * j], acc[2 * j + 1]);
        __syncthreads();
        if (tid < GCW) {
            float s = 0.f;
#pragma unroll
            for (int g = 0; g < 16; g++) s += part[g * GCW + tid];
            g_r[(size_t)(t * W_ + w) * TWOD + chunk * GCW + tid] = s;
        }
    }
}

// ---------------------------------------------------------------------------
// Small-M k-split GEMM: Cm += A[k-slice] @ B[k-slice] (atomicAdd), bias from z==0.
// RELUA applies relu to A elements on load. BM=32, BN=64, BK=16, 256 threads.
template <bool RELUA>
__global__ __launch_bounds__(256) void gemm_ks(const float* __restrict__ A,
                                               const float* __restrict__ B,
                                               const float* __restrict__ bias,
                                               float bscale,
                                               float* __restrict__ Cm,
                                               int M, int N, int Kd) {
    __shared__ float As[16][33];
    __shared__ float Bs[16][64];
    int col0 = blockIdx.x * 64;
    int row0 = blockIdx.y * 32;
    int tid = threadIdx.x;
    int tx = tid & 15, ty = tid >> 4;
    int klen = Kd / gridDim.z;
    int kbeg = blockIdx.z * klen, kend = kbeg + klen;
    float acc[2][4] = {};

    for (int k0 = kbeg; k0 < kend; k0 += 16) {
#pragma unroll
        for (int l = 0; l < 2; l++) {
            int e = tid + l * 256;
            int m = e >> 4, kk = e & 15;
            float v = A[(size_t)(row0 + m) * Kd + k0 + kk];
            if (RELUA) v = fmaxf(v, 0.f);
            As[kk][m] = v;
        }
        {
            int kk = tid >> 4, c = (tid & 15) * 4;
            *(float4*)&Bs[kk][c] = *(const float4*)(B + (size_t)(k0 + kk) * N + col0 + c);
        }
        __syncthreads();
#pragma unroll
        for (int kk = 0; kk < 16; kk++) {
            float a0 = As[kk][ty * 2], a1 = As[kk][ty * 2 + 1];
            float4 b = *(const float4*)&Bs[kk][tx * 4];
            acc[0][0] = fmaf(a0, b.x, acc[0][0]);
            acc[0][1] = fmaf(a0, b.y, acc[0][1]);
            acc[0][2] = fmaf(a0, b.z, acc[0][2]);
            acc[0][3] = fmaf(a0, b.w, acc[0][3]);
            acc[1][0] = fmaf(a1, b.x, acc[1][0]);
            acc[1][1] = fmaf(a1, b.y, acc[1][1]);
            acc[1][2] = fmaf(a1, b.z, acc[1][2]);
            acc[1][3] = fmaf(a1, b.w, acc[1][3]);
        }
        __syncthreads();
    }
#pragma unroll
    for (int i = 0; i < 2; i++) {
        int row = row0 + ty * 2 + i;
#pragma unroll
        for (int j = 0; j < 4; j++) {
            int colx = col0 + tx * 4 + j;
            float v = acc[i][j];
            if (blockIdx.z == 0) v += bias[colx] * bscale;
            atomicAdd(&Cm[(size_t)row * N + colx], v);
        }
    }
}

// ---------------------------------------------------------------------------
// score = o @ Wc + bc, softmax over C_=64. One block (64 threads) per row.
__global__ __launch_bounds__(64) void score_softmax(const float* __restrict__ Wc,
                                                    const float* __restrict__ bc,
                                                    float* __restrict__ out) {
    int row = blockIdx.x;
    int tid = threadIdx.x;
    __shared__ float so[D_];
    for (int e = tid; e < D_; e += 64) so[e] = g_o[(size_t)row * D_ + e];
    __syncthreads();

    float acc = bc[tid];
#pragma unroll 4
    for (int k = 0; k < D_; k++) acc = fmaf(so[k], Wc[(size_t)k * C_ + tid], acc);

    __shared__ float red[2], red2[2];
    float m = acc;
#pragma unroll
    for (int off = 16; off > 0; off >>= 1) m = fmaxf(m, __shfl_xor_sync(0xffffffffu, m, off));
    if ((tid & 31) == 0) red[tid >> 5] = m;
    __syncthreads();
    m = fmaxf(red[0], red[1]);

    float e = expf(acc - m);
    float s = e;
#pragma unroll
    for (int off = 16; off > 0; off >>= 1) s += __shfl_xor_sync(0xffffffffu, s, off);
    if ((tid & 31) == 0) red2[tid >> 5] = s;
    __syncthreads();
    s = red2[0] + red2[1];

    out[(size_t)row * C_ + tid] = e / s;
}

// ---------------------------------------------------------------------------
extern "C" void kernel_launch(void* const* d_in, const int* in_sizes, int n_in,
                              void* d_out, int out_size) {
    const float* x    = (const float*)d_in[0];
    const void*  tidx = d_in[1];                 // int32 or int64 — probed on device
    const float* W1   = (const float*)d_in[2];
    const float* b1   = (const float*)d_in[3];
    const float* W2   = (const float*)d_in[4];
    const float* b2   = (const float*)d_in[5];
    const float* W3   = (const float*)d_in[6];
    const float* b3   = (const float*)d_in[7];
    const float* W4   = (const float*)d_in[8];
    const float* b4   = (const float*)d_in[9];
    const float* Wc   = (const float*)d_in[10];
    const float* bc   = (const float*)d_in[11];
    float* out = (float*)d_out;

    void *pr, *pg, *ph3, *po;
    cudaGetSymbolAddress(&pr, g_r);
    cudaGetSymbolAddress(&pg, g_g);
    cudaGetSymbolAddress(&ph3, g_h3);
    cudaGetSymbolAddress(&po, g_o);

    cudaFuncSetAttribute(gemm_fp16, cudaFuncAttributeMaxDynamicSharedMemorySize,
                         GEMM_SMEM);
    cudaFuncSetAttribute(gather_s, cudaFuncAttributeMaxDynamicSharedMemorySize,
                         GSM_BYTES);

    // Launch order: gemm_fp16 is the 4th launch — ncu empirically captures #4.
    prep_a<<<(M_ * D_ / 4 + 255) / 256, 256>>>(x);                    // 1
    prep_b<<<(NP * D_ + 255) / 256, 256>>>(W1);                       // 2
    probe_reset<<<1, 1>>>();                                          // 3

    // 4) P(fp16) = A @ B^T  (fp16 GEMM, K=512, 3-stage cp.async, 2 CTAs/SM)
    gemm_fp16<<<dim3(NP / 128, M_ / 128), 256, GEMM_SMEM>>>();

    probe_idx<<<120, 256>>>((const unsigned int*)tidx);               // 5
    norm_idx<<<(NIDX + 255) / 256, 256>>>((const int*)tidx);          // 6
    zero_gho<<<(T_ * W_ * TWOD + 255) / 256, 256>>>();                // 7

    // 8) smem-staged gather+relu+k-sum -> r (direct store)
    gather_s<<<dim3(TWOD / GCW, T_), 256, GSM_BYTES>>>(b1);

    // 9) g = r @ W2 + K_*b2        (160 x 512, K=1024, 4-way k-split)
    gemm_ks<false><<<dim3(D_ / 64, 5, 4), 256>>>(
        (const float*)pr, W2, b2, (float)K_, (float*)pg, T_ * W_, D_, TWOD);

    // 10) h3_pre = g @ W3 + b3     (160 x 1024, K=512, 4-way k-split; relu deferred)
    gemm_ks<false><<<dim3(TWOD / 64, 5, 4), 256>>>(
        (const float*)pg, W3, b3, 1.f, (float*)ph3, T_ * W_, TWOD, D_);

    // 11) o = relu(h3_pre) @ W4 + b4 (160 x 512, K=1024, relu applied on A load)
    gemm_ks<true><<<dim3(D_ / 64, 5, 4), 256>>>(
        (const float*)ph3, W4, b4, 1.f, (float*)po, T_ * W_, D_, TWOD);

    // 12) score + softmax -> out   (160 x 64)
    score_softmax<<<T_ * W_, 64>>>(Wc, bc, out);
}

// round 12
// speedup vs baseline: 2.9465x; 1.2700x over previous
#include <cuda_runtime.h>
#include <cuda_fp16.h>
#include <mma.h>
#include <cstdint>

using namespace nvcuda;

#define T_ 16
#define S_ 16
#define W_ 10
#define D_ 512
#define C_ 64
#define K_ 512
#define SW 160        // S_*W_
#define TWOD 1024
#define NP 3072       // 3 * TWOD
#define NIDX (T_ * W_ * 3 * K_)   // 245760 indices
#define M_ (T_ * SW)              // 2560 rows of P

// ---------------------------------------------------------------------------
// Device globals (no allocation allowed)
__device__ __half g_Ah[(size_t)M_ * D_];  // [2560][512] fp16 A
__device__ __half g_Bh[(size_t)NP * D_];  // [3072][512] fp16 B^T
__device__ __half g_Ph[(size_t)M_ * NP];  // P in fp16  [2560][3072]
__device__ float g_r[T_ * W_ * TWOD];     // 160 x 1024  sum_k relu(z)
__device__ float g_g[T_ * W_ * D_];       // 160 x 512
__device__ float g_h3[T_ * W_ * TWOD];    // 160 x 1024 (pre-relu)
__device__ float g_o[T_ * W_ * D_];       // 160 x 512
__device__ unsigned int g_oddor;          // dtype probe result

// ---------------------------------------------------------------------------
__device__ __forceinline__ void cp_async16(void* dst, const void* src) {
    uint32_t d;
    asm("{ .reg .u64 t; cvta.to.shared.u64 t, %1; cvt.u32.u64 %0, t; }" : "=r"(d) : "l"(dst));
    asm volatile("cp.async.cg.shared.global [%0], [%1], 16;" :: "r"(d), "l"(src));
}

// ---------------------------------------------------------------------------
// probe: OR all odd 32-bit words. int64 layout -> 0 (high halves of small ints);
// int32 layout -> nonzero w.h.p. (real indices in odd slots). g_oddor reset by prep_a.
__global__ void probe_idx(const unsigned int* __restrict__ raw) {
    unsigned int v = 0;
    for (int i = blockIdx.x * 256 + threadIdx.x; i < NIDX / 2; i += gridDim.x * 256)
        v |= raw[2 * i + 1];
#pragma unroll
    for (int off = 16; off > 0; off >>= 1) v |= __shfl_xor_sync(0xffffffffu, v, off);
    if ((threadIdx.x & 31) == 0 && v) atomicOr(&g_oddor, v);
}

// ---------------------------------------------------------------------------
// X (2560x512 fp32) -> fp16 A; also zeros g/h3/o accumulators and g_oddor.
__global__ void prep_a(const float* __restrict__ x) {
    int i = blockIdx.x * 256 + threadIdx.x;     // i indexes groups of 4 elements
    if (i == 0) g_oddor = 0u;
    if (i < T_ * W_ * TWOD) g_h3[i] = 0.f;
    if (i < T_ * W_ * D_) { g_g[i] = 0.f; g_o[i] = 0.f; }
    if (i >= M_ * D_ / 4) return;
    float4 v = *(const float4*)(x + (size_t)i * 4);
    __half2 h0 = __floats2half2_rn(v.x, v.y);
    __half2 h1 = __floats2half2_rn(v.z, v.w);
    uint2 o = {*(uint32_t*)&h0, *(uint32_t*)&h1};
    *(uint2*)(g_Ah + (size_t)i * 4) = o;
}

// W1 (1536 x 1024) -> fp16 B^T [3072][512] via coalesced 32x32 smem transpose.
// B^T[s*1024+o][k] = W1[s*512+k][o]. grid (32, 16, 3), block 256.
__global__ __launch_bounds__(256) void prep_b(const float* __restrict__ W1) {
    __shared__ float tile[32][33];
    int o0 = blockIdx.x * 32, k0 = blockIdx.y * 32, s = blockIdx.z;
    int tx = threadIdx.x & 31, ty = threadIdx.x >> 5;   // ty 0..7
#pragma unroll
    for (int i = 0; i < 4; i++) {
        int k = ty + i * 8;
        tile[k][tx] = W1[(size_t)(s * D_ + k0 + k) * TWOD + o0 + tx];
    }
    __syncthreads();
#pragma unroll
    for (int i = 0; i < 4; i++) {
        int o = ty + i * 8;
        g_Bh[(size_t)(s * TWOD + o0 + o) * D_ + k0 + tx] = __float2half_rn(tile[tx][o]);
    }
}

// ---------------------------------------------------------------------------
// fp16 GEMM, fp32 accum: P(fp16 2560x3072) = A (2560x512) @ B^T (3072x512)
// CTA 128x128, 8 warps (warp tile 32x64), BK=32, 4-stage cp.async ring,
// single __syncthreads per chunk, 2 CTAs/SM (82KB smem).
#define BK 32
#define KPAD 40
#define STG (128 * KPAD)             // halves per matrix per stage (5120)
#define NSTAGE 4
#define NCH (D_ / BK)                // 16 chunks
#define GEMM_SMEM (NSTAGE * 2 * STG * 2)   // 81920 bytes

__global__ __launch_bounds__(256, 2) void gemm_fp16() {
    extern __shared__ __half sh[];   // [4 stages][A 128x40 | B 128x40]

    int tid = threadIdx.x;
    int wid = tid >> 5, lane = tid & 31;
    int warp_m = wid & 3;    // 4 warps along M -> 32 rows each
    int warp_n = wid >> 2;   // 2 warps along N -> 64 cols each
    int row0 = blockIdx.y * 128;
    int col0 = blockIdx.x * 128;

    wmma::fragment<wmma::accumulator, 16, 16, 16, float> acc[2][4];
#pragma unroll
    for (int i = 0; i < 2; i++)
#pragma unroll
        for (int j = 0; j < 4; j++) wmma::fill_fragment(acc[i][j], 0.f);

    auto prefetch = [&](int c) {
        int s = c % NSTAGE;
        __half* As = sh + s * (2 * STG);
        __half* Bs = As + STG;
        int k0 = c * BK;
#pragma unroll
        for (int j = 0; j < 2; j++) {
            int idx = tid + j * 256;
            int r = idx >> 2, q = (idx & 3) * 8;
            cp_async16(&As[r * KPAD + q], g_Ah + (size_t)(row0 + r) * D_ + k0 + q);
            cp_async16(&Bs[r * KPAD + q], g_Bh + (size_t)(col0 + r) * D_ + k0 + q);
        }
        asm volatile("cp.async.commit_group;" ::: "memory");
    };

    prefetch(0);
    prefetch(1);
    prefetch(2);
    for (int c = 0; c < NCH; c++) {
        // groups issued beyond c at this point = min(2, NCH-1-c)
        if (c < NCH - 2) {
            asm volatile("cp.async.wait_group 2;" ::: "memory");
        } else if (c == NCH - 2) {
            asm volatile("cp.async.wait_group 1;" ::: "memory");
        } else {
            asm volatile("cp.async.wait_group 0;" ::: "memory");
        }
        __syncthreads();   // stage c visible; all warps done with compute(c-1)
        if (c + 3 < NCH) prefetch(c + 3);   // writes stage (c-1)%4 — free now

        const __half* As = sh + (c % NSTAGE) * (2 * STG);
        const __half* Bs = As + STG;
#pragma unroll
        for (int kk = 0; kk < BK; kk += 16) {
            wmma::fragment<wmma::matrix_a, 16, 16, 16, __half, wmma::row_major> fa[2];
            wmma::fragment<wmma::matrix_b, 16, 16, 16, __half, wmma::col_major> fb[4];
#pragma unroll
            for (int i = 0; i < 2; i++)
                wmma::load_matrix_sync(fa[i], As + (warp_m * 32 + i * 16) * KPAD + kk, KPAD);
#pragma unroll
            for (int j = 0; j < 4; j++)
                wmma::load_matrix_sync(fb[j], Bs + (warp_n * 64 + j * 16) * KPAD + kk, KPAD);
#pragma unroll
            for (int i = 0; i < 2; i++)
#pragma unroll
                for (int j = 0; j < 4; j++)
                    wmma::mma_sync(acc[i][j], fa[i], fb[j], acc[i][j]);
        }
    }
    __syncthreads();   // all compute done before smem reuse as epilogue scratch

    // Epilogue: per-warp 16x16 float patch in smem, convert to fp16, store P.
    float* patch = (float*)sh + wid * 256;
#pragma unroll
    for (int i = 0; i < 2; i++)
#pragma unroll
        for (int j = 0; j < 4; j++) {
            wmma::store_matrix_sync(patch, acc[i][j], 16, wmma::mem_row_major);
            __syncwarp();
            int m = row0 + warp_m * 32 + i * 16;
            int n = col0 + warp_n * 64 + j * 16;
            int pr = lane >> 1, pc = (lane & 1) * 8;
            __half2 o[4];
#pragma unroll
            for (int e = 0; e < 4; e++)
                o[e] = __floats2half2_rn(patch[pr * 16 + pc + 2 * e],
                                         patch[pr * 16 + pc + 2 * e + 1]);
            *(uint4*)(g_Ph + (size_t)(m + pr) * NP + n + pc) = *(uint4*)o;
            __syncwarp();
        }
}

// ---------------------------------------------------------------------------
// Smem-staged gather: block = (chunk, t). Stages Ps[3][160][128] (123KB) once,
// serves all w,k row-reads from smem. 256 threads = 16 col-slots x 16 k-groups.
// Index dtype resolved inline via g_oddor (set by probe_idx).
#define GCW 128
#define PS_HALVES (3 * SW * GCW)               // 61440 halves
#define GSM_BYTES (PS_HALVES * 2 + 3 * K_ * 4 + 16 * GCW * 4)  // 137216

__global__ __launch_bounds__(256, 1) void gather_s(const float* __restrict__ b1,
                                                   const int* __restrict__ raw) {
    extern __shared__ char gsm[];
    __half* Ps  = (__half*)gsm;                              // [3][160][128]
    int*   sidx = (int*)(gsm + PS_HALVES * 2);               // [3][512]
    float* part = (float*)(gsm + PS_HALVES * 2 + 3 * K_ * 4); // [16][128]

    int chunk = blockIdx.x;   // 0..7 (128-col chunks of the 1024-wide output)
    int t     = blockIdx.y;   // 0..15
    int tid = threadIdx.x;
    unsigned int is32 = g_oddor;

    // Stage P slice: slot s, row n, cols [s*1024 + chunk*128, +128)
    const __half* Pt = g_Ph + (size_t)t * SW * NP;
    for (int i = tid; i < PS_HALVES / 8; i += 256) {   // 7680 uint4
        int q = i & 15;                // uint4 within row
        int r = (i >> 4) % SW;
        int s = i / (16 * SW);
        *(uint4*)(Ps + (s * SW + r) * GCW + q * 8) =
            *(const uint4*)(Pt + (size_t)r * NP + s * 1024 + chunk * GCW + q * 8);
    }

    int cs = (tid & 15) * 8;          // col-slot: 8 halves
    int kg = tid >> 4;                // k-group: 32 k each
    int col = chunk * GCW + cs;
    float bb[8];
#pragma unroll
    for (int j = 0; j < 8; j++) bb[j] = b1[col + j];

    for (int w = 0; w < W_; w++) {
        __syncthreads();   // staging done (w=0) / part+sidx consumers done (w>0)
        int base = (t * W_ + w) * 3 * K_;
        for (int i = tid; i < 3 * K_; i += 256) {
            int v = is32 ? raw[base + i] : raw[2 * (base + i)];
            sidx[i] = min(max(v, 0), SW - 1);
        }
        __syncthreads();

        float acc[8] = {};
#pragma unroll 4
        for (int k = kg * 32; k < kg * 32 + 32; k++) {
            int a = sidx[k];
            int b = sidx[K_ + k];
            int c = sidx[2 * K_ + k];
            uint4 va = *(uint4*)(Ps + (size_t)a * GCW + cs);
            uint4 vb = *(uint4*)(Ps + (SW + (size_t)b) * GCW + cs);
            uint4 vc = *(uint4*)(Ps + (2 * SW + (size_t)c) * GCW + cs);
            const __half2* ha = (const __half2*)&va;
            const __half2* hb = (const __half2*)&vb;
            const __half2* hc = (const __half2*)&vc;
#pragma unroll
            for (int j = 0; j < 4; j++) {
                float2 fa = __half22float2(ha[j]);
                float2 fb = __half22float2(hb[j]);
                float2 fc = __half22float2(hc[j]);
                float z0 = fa.x + fb.x + fc.x + bb[2 * j];
                float z1 = fa.y + fb.y + fc.y + bb[2 * j + 1];
                acc[2 * j]     += fmaxf(z0, 0.f);
                acc[2 * j + 1] += fmaxf(z1, 0.f);
            }
        }
        // partials -> smem, tree-reduce across the 16 k-groups
#pragma unroll
        for (int j = 0; j < 4; j++)
            *(float2*)&part[kg * GCW + cs + 2 * j] = make_float2(acc[2 * j], acc[2 * j + 1]);
        __syncthreads();
        if (tid < GCW) {
            float s = 0.f;
#pragma unroll
            for (int g = 0; g < 16; g++) s += part[g * GCW + tid];
            g_r[(size_t)(t * W_ + w) * TWOD + chunk * GCW + tid] = s;
        }
    }
}

// ---------------------------------------------------------------------------
// Small-M k-split GEMM: Cm += A[k-slice] @ B[k-slice] (atomicAdd), bias from z==0.
// RELUA applies relu to A elements on load. BM=32, BN=64, BK=16, 256 threads.
template <bool RELUA>
__global__ __launch_bounds__(256) void gemm_ks(const float* __restrict__ A,
                                               const float* __restrict__ B,
                                               const float* __restrict__ bias,
                                               float bscale,
                                               float* __restrict__ Cm,
                                               int M, int N, int Kd) {
    __shared__ float As[16][33];
    __shared__ float Bs[16][64];
    int col0 = blockIdx.x * 64;
    int row0 = blockIdx.y * 32;
    int tid = threadIdx.x;
    int tx = tid & 15, ty = tid >> 4;
    int klen = Kd / gridDim.z;
    int kbeg = blockIdx.z * klen, kend = kbeg + klen;
    float acc[2][4] = {};

    for (int k0 = kbeg; k0 < kend; k0 += 16) {
#pragma unroll
        for (int l = 0; l < 2; l++) {
            int e = tid + l * 256;
            int m = e >> 4, kk = e & 15;
            float v = A[(size_t)(row0 + m) * Kd + k0 + kk];
            if (RELUA) v = fmaxf(v, 0.f);
            As[kk][m] = v;
        }
        {
            int kk = tid >> 4, c = (tid & 15) * 4;
            *(float4*)&Bs[kk][c] = *(const float4*)(B + (size_t)(k0 + kk) * N + col0 + c);
        }
        __syncthreads();
#pragma unroll
        for (int kk = 0; kk < 16; kk++) {
            float a0 = As[kk][ty * 2], a1 = As[kk][ty * 2 + 1];
            float4 b = *(const float4*)&Bs[kk][tx * 4];
            acc[0][0] = fmaf(a0, b.x, acc[0][0]);
            acc[0][1] = fmaf(a0, b.y, acc[0][1]);
            acc[0][2] = fmaf(a0, b.z, acc[0][2]);
            acc[0][3] = fmaf(a0, b.w, acc[0][3]);
            acc[1][0] = fmaf(a1, b.x, acc[1][0]);
            acc[1][1] = fmaf(a1, b.y, acc[1][1]);
            acc[1][2] = fmaf(a1, b.z, acc[1][2]);
            acc[1][3] = fmaf(a1, b.w, acc[1][3]);
        }
        __syncthreads();
    }
#pragma unroll
    for (int i = 0; i < 2; i++) {
        int row = row0 + ty * 2 + i;
#pragma unroll
        for (int j = 0; j < 4; j++) {
            int colx = col0 + tx * 4 + j;
            float v = acc[i][j];
            if (blockIdx.z == 0) v += bias[colx] * bscale;
            atomicAdd(&Cm[(size_t)row * N + colx], v);
        }
    }
}

// ---------------------------------------------------------------------------
// score = o @ Wc + bc, softmax over C_=64. 256 threads: 64 cols x 4 k-slices.
__global__ __launch_bounds__(256) void score_softmax(const float* __restrict__ Wc,
                                                     const float* __restrict__ bc,
                                                     float* __restrict__ out) {
    int row = blockIdx.x;
    int tid = threadIdx.x;
    __shared__ float so[D_];
    __shared__ float part[4][C_];
    __shared__ float red[2], red2[2];
    for (int e = tid; e < D_; e += 256) so[e] = g_o[(size_t)row * D_ + e];
    __syncthreads();

    int col = tid & 63, sl = tid >> 6;
    float acc = (sl == 0) ? bc[col] : 0.f;
#pragma unroll 4
    for (int k = sl * 128; k < sl * 128 + 128; k++)
        acc = fmaf(so[k], Wc[(size_t)k * C_ + col], acc);
    part[sl][col] = acc;
    __syncthreads();

    float sc = 0.f, e = 0.f;
    if (tid < C_) {
        sc = part[0][tid] + part[1][tid] + part[2][tid] + part[3][tid];
        float m = sc;
#pragma unroll
        for (int off = 16; off > 0; off >>= 1) m = fmaxf(m, __shfl_xor_sync(0xffffffffu, m, off));
        if ((tid & 31) == 0) red[tid >> 5] = m;
    }
    __syncthreads();
    if (tid < C_) {
        float m = fmaxf(red[0], red[1]);
        e = expf(sc - m);
        float s = e;
#pragma unroll
        for (int off = 16; off > 0; off >>= 1) s += __shfl_xor_sync(0xffffffffu, s, off);
        if ((tid & 31) == 0) red2[tid >> 5] = s;
    }
    __syncthreads();
    if (tid < C_) out[(size_t)row * C_ + tid] = e / (red2[0] + red2[1]);
}

// ---------------------------------------------------------------------------
extern "C" void kernel_launch(void* const* d_in, const int* in_sizes, int n_in,
                              void* d_out, int out_size) {
    const float* x    = (const float*)d_in[0];
    const void*  tidx = d_in[1];                 // int32 or int64 — probed on device
    const float* W1   = (const float*)d_in[2];
    const float* b1   = (const float*)d_in[3];
    const float* W2   = (const float*)d_in[4];
    const float* b2   = (const float*)d_in[5];
    const float* W3   = (const float*)d_in[6];
    const float* b3   = (const float*)d_in[7];
    const float* W4   = (const float*)d_in[8];
    const float* b4   = (const float*)d_in[9];
    const float* Wc   = (const float*)d_in[10];
    const float* bc   = (const float*)d_in[11];
    float* out = (float*)d_out;

    void *pr, *pg, *ph3, *po;
    cudaGetSymbolAddress(&pr, g_r);
    cudaGetSymbolAddress(&pg, g_g);
    cudaGetSymbolAddress(&ph3, g_h3);
    cudaGetSymbolAddress(&po, g_o);

    cudaFuncSetAttribute(gemm_fp16, cudaFuncAttributeMaxDynamicSharedMemorySize,
                         GEMM_SMEM);
    cudaFuncSetAttribute(gather_s, cudaFuncAttributeMaxDynamicSharedMemorySize,
                         GSM_BYTES);

    // 1) fp16 A + zero accumulators + reset probe flag
    prep_a<<<(M_ * D_ / 4 + 255) / 256, 256>>>(x);
    // 2) fp16 B^T (coalesced transpose)
    prep_b<<<dim3(TWOD / 32, D_ / 32, 3), 256>>>(W1);
    // 3) index dtype probe
    probe_idx<<<120, 256>>>((const unsigned int*)tidx);

    // 4) P(fp16) = A @ B^T  (fp16 GEMM, K=512, 4-stage cp.async, 2 CTAs/SM)
    gemm_fp16<<<dim3(NP / 128, M_ / 128), 256, GEMM_SMEM>>>();

    // 5) smem-staged gather+relu+k-sum -> r (direct store; inline idx decode)
    gather_s<<<dim3(TWOD / GCW, T_), 256, GSM_BYTES>>>(b1, (const int*)tidx);

    // 6) g = r @ W2 + K_*b2        (160 x 512, K=1024, 8-way k-split)
    gemm_ks<false><<<dim3(D_ / 64, 5, 8), 256>>>(
        (const float*)pr, W2, b2, (float)K_, (float*)pg, T_ * W_, D_, TWOD);

    // 7) h3_pre = g @ W3 + b3      (160 x 1024, K=512, 4-way k-split; relu deferred)
    gemm_ks<false><<<dim3(TWOD / 64, 5, 4), 256>>>(
        (const float*)pg, W3, b3, 1.f, (float*)ph3, T_ * W_, TWOD, D_);

    // 8) o = relu(h3_pre) @ W4 + b4 (160 x 512, K=1024, 8-way k-split)
    gemm_ks<true><<<dim3(D_ / 64, 5, 8), 256>>>(
        (const float*)ph3, W4, b4, 1.f, (float*)po, T_ * W_, D_, TWOD);

    // 9) score + softmax -> out    (160 x 64)
    score_softmax<<<T_ * W_, 256>>>(Wc, bc, out);
}

// round 13
// speedup vs baseline: 3.2219x; 1.0935x over previous
#include <cuda_runtime.h>
#include <cuda_fp16.h>
#include <mma.h>
#include <cstdint>

using namespace nvcuda;

#define T_ 16
#define S_ 16
#define W_ 10
#define D_ 512
#define C_ 64
#define K_ 512
#define SW 160        // S_*W_
#define TWOD 1024
#define NP 3072       // 3 * TWOD
#define NIDX (T_ * W_ * 3 * K_)   // 245760 indices
#define M_ (T_ * SW)              // 2560 rows of P

// ---------------------------------------------------------------------------
// Device globals (no allocation allowed)
__device__ __half g_Ah[(size_t)M_ * D_];  // [2560][512] fp16 A
__device__ __half g_Bh[(size_t)NP * D_];  // [3072][512] fp16 B^T
__device__ __half g_Ph[(size_t)M_ * NP];  // P in fp16  [2560][3072]
__device__ float g_r[T_ * W_ * TWOD];     // 160 x 1024  sum_k relu(z)
__device__ float g_g[T_ * W_ * D_];       // 160 x 512
__device__ float g_h3[T_ * W_ * TWOD];    // 160 x 1024 (pre-relu)
__device__ float g_o[T_ * W_ * D_];       // 160 x 512
__device__ unsigned int g_oddor = 0u;     // dtype probe (never reset: atomicOr over
                                          // identical data is idempotent => deterministic)

// ---------------------------------------------------------------------------
__device__ __forceinline__ void cp_async16(void* dst, const void* src) {
    uint32_t d;
    asm("{ .reg .u64 t; cvta.to.shared.u64 t, %1; cvt.u32.u64 %0, t; }" : "=r"(d) : "l"(dst));
    asm volatile("cp.async.cg.shared.global [%0], [%1], 16;" :: "r"(d), "l"(src));
}

// ---------------------------------------------------------------------------
// X (2560x512 fp32) -> fp16 A; zeros g/h3/o; inline dtype probe (odd-word OR:
// int64 layout -> 0, int32 layout -> nonzero w.h.p.).
__global__ void prep_a(const float* __restrict__ x, const unsigned int* __restrict__ raw) {
    int i = blockIdx.x * 256 + threadIdx.x;     // i indexes groups of 4 elements
    unsigned int v = (i < NIDX / 2) ? raw[2 * i + 1] : 0u;
#pragma unroll
    for (int off = 16; off > 0; off >>= 1) v |= __shfl_xor_sync(0xffffffffu, v, off);
    if ((threadIdx.x & 31) == 0 && v) atomicOr(&g_oddor, v);

    if (i < T_ * W_ * TWOD) g_h3[i] = 0.f;
    if (i < T_ * W_ * D_) { g_g[i] = 0.f; g_o[i] = 0.f; }
    if (i >= M_ * D_ / 4) return;
    float4 vv = *(const float4*)(x + (size_t)i * 4);
    __half2 h0 = __floats2half2_rn(vv.x, vv.y);
    __half2 h1 = __floats2half2_rn(vv.z, vv.w);
    uint2 o = {*(uint32_t*)&h0, *(uint32_t*)&h1};
    *(uint2*)(g_Ah + (size_t)i * 4) = o;
}

// W1 (1536 x 1024) -> fp16 B^T [3072][512] via coalesced 32x32 smem transpose.
__global__ __launch_bounds__(256) void prep_b(const float* __restrict__ W1) {
    __shared__ float tile[32][33];
    int o0 = blockIdx.x * 32, k0 = blockIdx.y * 32, s = blockIdx.z;
    int tx = threadIdx.x & 31, ty = threadIdx.x >> 5;   // ty 0..7
#pragma unroll
    for (int i = 0; i < 4; i++) {
        int k = ty + i * 8;
        tile[k][tx] = W1[(size_t)(s * D_ + k0 + k) * TWOD + o0 + tx];
    }
    __syncthreads();
#pragma unroll
    for (int i = 0; i < 4; i++) {
        int o = ty + i * 8;
        g_Bh[(size_t)(s * TWOD + o0 + o) * D_ + k0 + tx] = __float2half_rn(tile[tx][o]);
    }
}

// ---------------------------------------------------------------------------
// fp16 GEMM, fp32 accum: P(fp16 2560x3072) = A (2560x512) @ B^T (3072x512)
// CTA 128x128, 8 warps (warp tile 32x64), BK=32, 4-stage cp.async ring, 2 CTAs/SM.
#define BK 32
#define KPAD 40
#define STG (128 * KPAD)             // halves per matrix per stage (5120)
#define NSTAGE 4
#define NCH (D_ / BK)                // 16 chunks
#define GEMM_SMEM (NSTAGE * 2 * STG * 2)   // 81920 bytes

__global__ __launch_bounds__(256, 2) void gemm_fp16() {
    extern __shared__ __half sh[];   // [4 stages][A 128x40 | B 128x40]

    int tid = threadIdx.x;
    int wid = tid >> 5, lane = tid & 31;
    int warp_m = wid & 3;    // 4 warps along M -> 32 rows each
    int warp_n = wid >> 2;   // 2 warps along N -> 64 cols each
    int row0 = blockIdx.y * 128;
    int col0 = blockIdx.x * 128;

    wmma::fragment<wmma::accumulator, 16, 16, 16, float> acc[2][4];
#pragma unroll
    for (int i = 0; i < 2; i++)
#pragma unroll
        for (int j = 0; j < 4; j++) wmma::fill_fragment(acc[i][j], 0.f);

    auto prefetch = [&](int c) {
        int s = c % NSTAGE;
        __half* As = sh + s * (2 * STG);
        __half* Bs = As + STG;
        int k0 = c * BK;
#pragma unroll
        for (int j = 0; j < 2; j++) {
            int idx = tid + j * 256;
            int r = idx >> 2, q = (idx & 3) * 8;
            cp_async16(&As[r * KPAD + q], g_Ah + (size_t)(row0 + r) * D_ + k0 + q);
            cp_async16(&Bs[r * KPAD + q], g_Bh + (size_t)(col0 + r) * D_ + k0 + q);
        }
        asm volatile("cp.async.commit_group;" ::: "memory");
    };

    prefetch(0);
    prefetch(1);
    prefetch(2);
    for (int c = 0; c < NCH; c++) {
        if (c < NCH - 2) {
            asm volatile("cp.async.wait_group 2;" ::: "memory");
        } else if (c == NCH - 2) {
            asm volatile("cp.async.wait_group 1;" ::: "memory");
        } else {
            asm volatile("cp.async.wait_group 0;" ::: "memory");
        }
        __syncthreads();
        if (c + 3 < NCH) prefetch(c + 3);

        const __half* As = sh + (c % NSTAGE) * (2 * STG);
        const __half* Bs = As + STG;
#pragma unroll
        for (int kk = 0; kk < BK; kk += 16) {
            wmma::fragment<wmma::matrix_a, 16, 16, 16, __half, wmma::row_major> fa[2];
            wmma::fragment<wmma::matrix_b, 16, 16, 16, __half, wmma::col_major> fb[4];
#pragma unroll
            for (int i = 0; i < 2; i++)
                wmma::load_matrix_sync(fa[i], As + (warp_m * 32 + i * 16) * KPAD + kk, KPAD);
#pragma unroll
            for (int j = 0; j < 4; j++)
                wmma::load_matrix_sync(fb[j], Bs + (warp_n * 64 + j * 16) * KPAD + kk, KPAD);
#pragma unroll
            for (int i = 0; i < 2; i++)
#pragma unroll
                for (int j = 0; j < 4; j++)
                    wmma::mma_sync(acc[i][j], fa[i], fb[j], acc[i][j]);
        }
    }
    __syncthreads();

    // Epilogue: per-warp 16x16 float patch in smem, convert to fp16, store P.
    float* patch = (float*)sh + wid * 256;
#pragma unroll
    for (int i = 0; i < 2; i++)
#pragma unroll
        for (int j = 0; j < 4; j++) {
            wmma::store_matrix_sync(patch, acc[i][j], 16, wmma::mem_row_major);
            __syncwarp();
            int m = row0 + warp_m * 32 + i * 16;
            int n = col0 + warp_n * 64 + j * 16;
            int pr = lane >> 1, pc = (lane & 1) * 8;
            __half2 o[4];
#pragma unroll
            for (int e = 0; e < 4; e++)
                o[e] = __floats2half2_rn(patch[pr * 16 + pc + 2 * e],
                                         patch[pr * 16 + pc + 2 * e + 1]);
            *(uint4*)(g_Ph + (size_t)(m + pr) * NP + n + pc) = *(uint4*)o;
            __syncwarp();
        }
}

// ---------------------------------------------------------------------------
// Smem-staged gather, GCW=64: block = (chunk, t), 2 CTAs/SM, 256 blocks.
// 256 threads = 8 col-slots x 32 k-groups (16 k each). half2 adds, fp32 accum.
#define GCW 64
#define NKG 32
#define PS_HALVES (3 * SW * GCW)               // 30720 halves
#define GSM_BYTES (PS_HALVES * 2 + 3 * K_ * 4 + NKG * GCW * 4)  // 75776

__global__ __launch_bounds__(256) void gather_s(const float* __restrict__ b1,
                                                const int* __restrict__ raw) {
    extern __shared__ char gsm[];
    __half* Ps  = (__half*)gsm;                              // [3][160][64]
    int*   sidx = (int*)(gsm + PS_HALVES * 2);               // [3][512]
    float* part = (float*)(gsm + PS_HALVES * 2 + 3 * K_ * 4); // [32][64]

    int chunk = blockIdx.x;   // 0..15 (64-col chunks of the 1024-wide output)
    int t     = blockIdx.y;   // 0..15
    int tid = threadIdx.x;
    unsigned int is32 = g_oddor;

    // Stage P slice: slot s, row r, cols [s*1024 + chunk*64, +64)
    const __half* Pt = g_Ph + (size_t)t * SW * NP;
    for (int i = tid; i < PS_HALVES / 8; i += 256) {   // 3840 uint4
        int q = i & 7;                 // uint4 within row (8 per 64-half row)
        int r = (i >> 3) % SW;
        int s = i / (8 * SW);
        *(uint4*)(Ps + (s * SW + r) * GCW + q * 8) =
            *(const uint4*)(Pt + (size_t)r * NP + s * 1024 + chunk * GCW + q * 8);
    }

    int cs = (tid & 7) * 8;           // col-slot: 8 halves
    int kg = tid >> 3;                // k-group: 16 k each
    int col = chunk * GCW + cs;
    __half2 bbh[4];
#pragma unroll
    for (int j = 0; j < 4; j++) bbh[j] = __floats2half2_rn(b1[col + 2 * j], b1[col + 2 * j + 1]);
    const __half2 zero2 = __floats2half2_rn(0.f, 0.f);

    for (int w = 0; w < W_; w++) {
        __syncthreads();   // staging done (w=0) / part consumers done (w>0)
        int base = (t * W_ + w) * 3 * K_;
        for (int i = tid; i < 3 * K_; i += 256) {
            int v = is32 ? raw[base + i] : raw[2 * (base + i)];
            sidx[i] = min(max(v, 0), SW - 1);
        }
        __syncthreads();

        float acc[8] = {};
#pragma unroll 4
        for (int k = kg * 16; k < kg * 16 + 16; k++) {
            int a = sidx[k];
            int b = sidx[K_ + k];
            int c = sidx[2 * K_ + k];
            uint4 va = *(uint4*)(Ps + (size_t)a * GCW + cs);
            uint4 vb = *(uint4*)(Ps + (SW + (size_t)b) * GCW + cs);
            uint4 vc = *(uint4*)(Ps + (2 * SW + (size_t)c) * GCW + cs);
            const __half2* ha = (const __half2*)&va;
            const __half2* hb = (const __half2*)&vb;
            const __half2* hc = (const __half2*)&vc;
#pragma unroll
            for (int j = 0; j < 4; j++) {
                __half2 z = __hadd2(__hadd2(ha[j], hb[j]), __hadd2(hc[j], bbh[j]));
                z = __hmax2(z, zero2);
                float2 f = __half22float2(z);
                acc[2 * j]     += f.x;
                acc[2 * j + 1] += f.y;
            }
        }
#pragma unroll
        for (int j = 0; j < 4; j++)
            *(float2*)&part[kg * GCW + cs + 2 * j] = make_float2(acc[2 * j], acc[2 * j + 1]);
        __syncthreads();
        if (tid < GCW) {
            float s = 0.f;
#pragma unroll
            for (int g = 0; g < NKG; g++) s += part[g * GCW + tid];
            g_r[(size_t)(t * W_ + w) * TWOD + chunk * GCW + tid] = s;
        }
    }
}

// ---------------------------------------------------------------------------
// Small-M k-split GEMM: Cm += A[k-slice] @ B[k-slice] (atomicAdd), bias from z==0.
// RELUA applies relu to A elements on load. BM=32, BN=64, BK=16, 256 threads.
template <bool RELUA>
__global__ __launch_bounds__(256) void gemm_ks(const float* __restrict__ A,
                                               const float* __restrict__ B,
                                               const float* __restrict__ bias,
                                               float bscale,
                                               float* __restrict__ Cm,
                                               int M, int N, int Kd) {
    __shared__ float As[16][33];
    __shared__ float Bs[16][64];
    int col0 = blockIdx.x * 64;
    int row0 = blockIdx.y * 32;
    int tid = threadIdx.x;
    int tx = tid & 15, ty = tid >> 4;
    int klen = Kd / gridDim.z;
    int kbeg = blockIdx.z * klen, kend = kbeg + klen;
    float acc[2][4] = {};

    for (int k0 = kbeg; k0 < kend; k0 += 16) {
#pragma unroll
        for (int l = 0; l < 2; l++) {
            int e = tid + l * 256;
            int m = e >> 4, kk = e & 15;
            float v = A[(size_t)(row0 + m) * Kd + k0 + kk];
            if (RELUA) v = fmaxf(v, 0.f);
            As[kk][m] = v;
        }
        {
            int kk = tid >> 4, c = (tid & 15) * 4;
            *(float4*)&Bs[kk][c] = *(const float4*)(B + (size_t)(k0 + kk) * N + col0 + c);
        }
        __syncthreads();
#pragma unroll
        for (int kk = 0; kk < 16; kk++) {
            float a0 = As[kk][ty * 2], a1 = As[kk][ty * 2 + 1];
            float4 b = *(const float4*)&Bs[kk][tx * 4];
            acc[0][0] = fmaf(a0, b.x, acc[0][0]);
            acc[0][1] = fmaf(a0, b.y, acc[0][1]);
            acc[0][2] = fmaf(a0, b.z, acc[0][2]);
            acc[0][3] = fmaf(a0, b.w, acc[0][3]);
            acc[1][0] = fmaf(a1, b.x, acc[1][0]);
            acc[1][1] = fmaf(a1, b.y, acc[1][1]);
            acc[1][2] = fmaf(a1, b.z, acc[1][2]);
            acc[1][3] = fmaf(a1, b.w, acc[1][3]);
        }
        __syncthreads();
    }
#pragma unroll
    for (int i = 0; i < 2; i++) {
        int row = row0 + ty * 2 + i;
#pragma unroll
        for (int j = 0; j < 4; j++) {
            int colx = col0 + tx * 4 + j;
            float v = acc[i][j];
            if (blockIdx.z == 0) v += bias[colx] * bscale;
            atomicAdd(&Cm[(size_t)row * N + colx], v);
        }
    }
}

// ---------------------------------------------------------------------------
// score = o @ Wc + bc, softmax over C_=64. 256 threads: 64 cols x 4 k-slices.
__global__ __launch_bounds__(256) void score_softmax(const float* __restrict__ Wc,
                                                     const float* __restrict__ bc,
                                                     float* __restrict__ out) {
    int row = blockIdx.x;
    int tid = threadIdx.x;
    __shared__ float so[D_];
    __shared__ float part[4][C_];
    __shared__ float red[2], red2[2];
    for (int e = tid; e < D_; e += 256) so[e] = g_o[(size_t)row * D_ + e];
    __syncthreads();

    int col = tid & 63, sl = tid >> 6;
    float acc = (sl == 0) ? bc[col] : 0.f;
#pragma unroll 4
    for (int k = sl * 128; k < sl * 128 + 128; k++)
        acc = fmaf(so[k], Wc[(size_t)k * C_ + col], acc);
    part[sl][col] = acc;
    __syncthreads();

    float sc = 0.f, e = 0.f;
    if (tid < C_) {
        sc = part[0][tid] + part[1][tid] + part[2][tid] + part[3][tid];
        float m = sc;
#pragma unroll
        for (int off = 16; off > 0; off >>= 1) m = fmaxf(m, __shfl_xor_sync(0xffffffffu, m, off));
        if ((tid & 31) == 0) red[tid >> 5] = m;
    }
    __syncthreads();
    if (tid < C_) {
        float m = fmaxf(red[0], red[1]);
        e = expf(sc - m);
        float s = e;
#pragma unroll
        for (int off = 16; off > 0; off >>= 1) s += __shfl_xor_sync(0xffffffffu, s, off);
        if ((tid & 31) == 0) red2[tid >> 5] = s;
    }
    __syncthreads();
    if (tid < C_) out[(size_t)row * C_ + tid] = e / (red2[0] + red2[1]);
}

// ---------------------------------------------------------------------------
extern "C" void kernel_launch(void* const* d_in, const int* in_sizes, int n_in,
                              void* d_out, int out_size) {
    const float* x    = (const float*)d_in[0];
    const void*  tidx = d_in[1];                 // int32 or int64 — probed on device
    const float* W1   = (const float*)d_in[2];
    const float* b1   = (const float*)d_in[3];
    const float* W2   = (const float*)d_in[4];
    const float* b2   = (const float*)d_in[5];
    const float* W3   = (const float*)d_in[6];
    const float* b3   = (const float*)d_in[7];
    const float* W4   = (const float*)d_in[8];
    const float* b4   = (const float*)d_in[9];
    const float* Wc   = (const float*)d_in[10];
    const float* bc   = (const float*)d_in[11];
    float* out = (float*)d_out;

    void *pr, *pg, *ph3, *po;
    cudaGetSymbolAddress(&pr, g_r);
    cudaGetSymbolAddress(&pg, g_g);
    cudaGetSymbolAddress(&ph3, g_h3);
    cudaGetSymbolAddress(&po, g_o);

    cudaFuncSetAttribute(gemm_fp16, cudaFuncAttributeMaxDynamicSharedMemorySize,
                         GEMM_SMEM);
    cudaFuncSetAttribute(gather_s, cudaFuncAttributeMaxDynamicSharedMemorySize,
                         GSM_BYTES);

    // 1) fp16 A + zero accumulators + inline dtype probe
    prep_a<<<(M_ * D_ / 4 + 255) / 256, 256>>>(x, (const unsigned int*)tidx);
    // 2) fp16 B^T (coalesced transpose)
    prep_b<<<dim3(TWOD / 32, D_ / 32, 3), 256>>>(W1);

    // 3) P(fp16) = A @ B^T  (fp16 GEMM, K=512, 4-stage cp.async, 2 CTAs/SM)
    gemm_fp16<<<dim3(NP / 128, M_ / 128), 256, GEMM_SMEM>>>();

    // 4) smem-staged gather+relu+k-sum -> r  (profiled slot)
    gather_s<<<dim3(TWOD / GCW, T_), 256, GSM_BYTES>>>(b1, (const int*)tidx);

    // 5) g = r @ W2 + K_*b2        (160 x 512, K=1024, 16-way k-split)
    gemm_ks<false><<<dim3(D_ / 64, 5, 16), 256>>>(
        (const float*)pr, W2, b2, (float)K_, (float*)pg, T_ * W_, D_, TWOD);

    // 6) h3_pre = g @ W3 + b3      (160 x 1024, K=512, 8-way k-split; relu deferred)
    gemm_ks<false><<<dim3(TWOD / 64, 5, 8), 256>>>(
        (const float*)pg, W3, b3, 1.f, (float*)ph3, T_ * W_, TWOD, D_);

    // 7) o = relu(h3_pre) @ W4 + b4 (160 x 512, K=1024, 16-way k-split)
    gemm_ks<true><<<dim3(D_ / 64, 5, 16), 256>>>(
        (const float*)ph3, W4, b4, 1.f, (float*)po, T_ * W_, D_, TWOD);

    // 8) score + softmax -> out    (160 x 64)
    score_softmax<<<T_ * W_, 256>>>(Wc, bc, out);
}